// round 13
// baseline (speedup 1.0000x reference)
#include <cuda_runtime.h>
#include <cuda_bf16.h>
#include <math.h>

#define EN 50000
#define RN 500
#define DN 256
#define NEDGE 500000
#define TWOD 512
#define HIDN 128
#define SLOPE 0.01f
#define KP 50048
#define TOTKB (KP / 32)
#define GEMM_Z 37
#define GEMM_KBPC 43
#define GSTR 40

// ---------------- static scratch ----------------
__device__ float g_pX2[EN * DN];
__device__ float g_gb[EN * DN];
__device__ float g_h1[EN * DN];
__device__ __nv_bfloat16 g_Xbf[EN * DN];
__device__ __nv_bfloat16 g_Xbf2[EN * DN];
__device__ __nv_bfloat16 g_Xbf3[EN * DN];
__device__ __nv_bfloat16 g_HT[1000 * KP];
__device__ __nv_bfloat16 g_XT[DN * KP];
__device__ __nv_bfloat16 g_KwT1[DN * DN];
__device__ __nv_bfloat16 g_KwT2[DN * DN];
__device__ __nv_bfloat16 g_coefbf[512 * 512];
__device__ __nv_bfloat16 g_valsT[512 * 512];
__device__ float g_LR[1000 * DN];
__device__ float g_cs[1000];
__device__ float g_dX[RN * TWOD];
__device__ float g_dH1[RN * TWOD];
__device__ float g_dH2[RN * TWOD];
__device__ float g_f1[RN];
__device__ float g_f2[RN];
__device__ float g_score[RN];
__device__ int g_cntE[EN];
__device__ int g_cntM[EN];
__device__ int g_curE[EN];
__device__ int g_curM[EN];
__device__ int g_erptr[EN + 1];
__device__ int g_eperm[NEDGE];
__device__ int g_mrptr[EN + 1];
__device__ int g_mperm[NEDGE];

// ---------------- fused X-transpose + global init + Kw prep ----------------
__global__ void k_prepX_init(const float* __restrict__ In, __nv_bfloat16* __restrict__ OutT,
                             __nv_bfloat16* __restrict__ Rowbf, float* __restrict__ LR,
                             float* __restrict__ cs, int* cE, int* cM,
                             const float* __restrict__ K1, const float* __restrict__ K2,
                             __nv_bfloat16* __restrict__ T1, __nv_bfloat16* __restrict__ T2) {
    if (blockIdx.y == 8) {
        int i = blockIdx.x * blockDim.x + threadIdx.x;
        if (i < 1000 * DN) LR[i] = 0.f;
        if (i < 1000) cs[i] = 0.f;
        if (i < EN) { cE[i] = 0; cM[i] = 0; }
        if (i < DN * DN) {
            int n = i >> 8, k = i & 255;
            T1[i] = __float2bfloat16(K1[k * DN + n]);
            T2[i] = __float2bfloat16(K2[k * DN + n]);
        }
        return;
    }
    __shared__ float tile[32][33];
    int e0 = blockIdx.x * 32, r0 = blockIdx.y * 32;
    int tx = threadIdx.x & 31, ty = threadIdx.x >> 5;
#pragma unroll
    for (int j = 0; j < 4; j++) {
        int e = e0 + ty + j * 8, r = r0 + tx;
        float v = (e < EN) ? In[(size_t)e * DN + r] : 0.f;
        tile[ty + j * 8][tx] = v;
        if (e < EN) Rowbf[(size_t)e * DN + r] = __float2bfloat16(v);
    }
    __syncthreads();
#pragma unroll
    for (int j = 0; j < 4; j++) {
        int r = r0 + ty + j * 8, e = e0 + tx;
        OutT[(size_t)r * KP + e] = __float2bfloat16(tile[tx][ty + j * 8]);
    }
}

// transpose In [EN][R] fp32 -> OutT [R][KP] bf16 (pad zero); optional colsum
__global__ void k_prepT(const float* __restrict__ In, __nv_bfloat16* __restrict__ OutT,
                        float* __restrict__ colsum, int R) {
    __shared__ float tile[32][33];
    int e0 = blockIdx.x * 32, r0 = blockIdx.y * 32;
    int tx = threadIdx.x & 31, ty = threadIdx.x >> 5;
#pragma unroll
    for (int j = 0; j < 4; j++) {
        int e = e0 + ty + j * 8, r = r0 + tx;
        tile[ty + j * 8][tx] = (e < EN && r < R) ? In[(size_t)e * R + r] : 0.f;
    }
    __syncthreads();
#pragma unroll
    for (int j = 0; j < 4; j++) {
        int r = r0 + ty + j * 8, e = e0 + tx;
        if (r < R) OutT[(size_t)r * KP + e] = __float2bfloat16(tile[tx][ty + j * 8]);
    }
    if (colsum && ty == 0 && r0 + tx < R) {
        float s = 0.f;
#pragma unroll
        for (int e = 0; e < 32; e++) s += tile[e][tx];
        atomicAdd(&colsum[r0 + tx], s);
    }
}

// transpose bf16 [EN][DN] -> [DN][KP] bf16 (pad zero); extra y-slice zeros LR
__global__ void k_transpTbf(const __nv_bfloat16* __restrict__ In,
                            __nv_bfloat16* __restrict__ OutT, float* __restrict__ LR) {
    if (blockIdx.y == 8) {
        int i = blockIdx.x * blockDim.x + threadIdx.x;
        if (i < 1000 * DN) LR[i] = 0.f;
        return;
    }
    __shared__ __nv_bfloat16 tile[32][33];
    int e0 = blockIdx.x * 32, r0 = blockIdx.y * 32;
    int tx = threadIdx.x & 31, ty = threadIdx.x >> 5;
#pragma unroll
    for (int j = 0; j < 4; j++) {
        int e = e0 + ty + j * 8, r = r0 + tx;
        tile[ty + j * 8][tx] = (e < EN) ? In[(size_t)e * DN + r] : __float2bfloat16(0.f);
    }
    __syncthreads();
#pragma unroll
    for (int j = 0; j < 4; j++) {
        int r = r0 + ty + j * 8, e = e0 + tx;
        OutT[(size_t)r * KP + e] = tile[tx][ty + j * 8];
    }
}

// vals [RN][512] fp32 -> valsT [512][512] bf16
__global__ void k_transpT(const float* __restrict__ in, __nv_bfloat16* __restrict__ out) {
    __shared__ float tile[32][33];
    int j0 = blockIdx.x * 32, d0 = blockIdx.y * 32;
    int tx = threadIdx.x & 31, ty = threadIdx.x >> 5;
#pragma unroll
    for (int jj = 0; jj < 4; jj++) {
        int j = j0 + ty + jj * 8;
        tile[ty + jj * 8][tx] = (j < RN) ? in[(size_t)j * TWOD + d0 + tx] : 0.f;
    }
    __syncthreads();
#pragma unroll
    for (int jj = 0; jj < 4; jj++) {
        int d = d0 + ty + jj * 8;
        out[(size_t)d * 512 + j0 + tx] = __float2bfloat16(tile[tx][ty + jj * 8]);
    }
}

// ---------------- CSR build (both graphs fused) ----------------
__global__ void k_hist2(const int* __restrict__ er, const int* __restrict__ mr, int* cE,
                        int* cM) {
    int i = blockIdx.x * blockDim.x + threadIdx.x;
    if (i < NEDGE) {
        atomicAdd(&cE[er[i]], 1);
        atomicAdd(&cM[mr[i]], 1);
    }
}
__global__ void k_scan2(const int* __restrict__ cA, int* __restrict__ pA, int* __restrict__ uA,
                        const int* __restrict__ cB, int* __restrict__ pB, int* __restrict__ uB) {
    __shared__ int wsum[32];
    __shared__ int s_run;
    int tid = threadIdx.x, lane = tid & 31, w = tid >> 5;
    for (int g = 0; g < 2; g++) {
        const int* cnt = g ? cB : cA;
        int* ptr = g ? pB : pA;
        int* cur = g ? uB : uA;
        if (tid == 0) s_run = 0;
        __syncthreads();
        for (int base = 0; base < EN; base += 1024) {
            int i = base + tid;
            int v = (i < EN) ? cnt[i] : 0;
            int x = v;
#pragma unroll
            for (int o = 1; o < 32; o <<= 1) {
                int y = __shfl_up_sync(0xffffffffu, x, o);
                if (lane >= o) x += y;
            }
            if (lane == 31) wsum[w] = x;
            __syncthreads();
            if (w == 0) {
                int s = wsum[lane];
#pragma unroll
                for (int o = 1; o < 32; o <<= 1) {
                    int y = __shfl_up_sync(0xffffffffu, s, o);
                    if (lane >= o) s += y;
                }
                wsum[lane] = s;
            }
            __syncthreads();
            int excl = s_run + x - v + (w ? wsum[w - 1] : 0);
            if (i < EN) { ptr[i] = excl; cur[i] = excl; }
            __syncthreads();
            if (tid == 1023) s_run += wsum[31];
            __syncthreads();
        }
        if (tid == 0) ptr[EN] = s_run;
        __syncthreads();
    }
}
__global__ void k_scatter2(const int* __restrict__ er, int* uE, int* __restrict__ pe,
                           const int* __restrict__ mr, int* uM, int* __restrict__ pm) {
    int i = blockIdx.x * blockDim.x + threadIdx.x;
    if (i < NEDGE) {
        pe[atomicAdd(&uE[er[i]], 1)] = i;
        pm[atomicAdd(&uM[mr[i]], 1)] = i;
    }
}

// ---------------- mma helpers ----------------
__device__ __forceinline__ void mma16816(float* c, unsigned a0, unsigned a1, unsigned a2,
                                         unsigned a3, unsigned b0, unsigned b1) {
    asm volatile(
        "mma.sync.aligned.m16n8k16.row.col.f32.bf16.bf16.f32 "
        "{%0,%1,%2,%3},{%4,%5,%6,%7},{%8,%9},{%0,%1,%2,%3};\n"
        : "+f"(c[0]), "+f"(c[1]), "+f"(c[2]), "+f"(c[3])
        : "r"(a0), "r"(a1), "r"(a2), "r"(a3), "r"(b0), "r"(b1));
}
__device__ __forceinline__ void cpa16(unsigned s, const void* g) {
    asm volatile("cp.async.cg.shared.global [%0], [%1], 16;\n" ::"r"(s), "l"(g));
}
__device__ __forceinline__ void ldsm4(unsigned* r, unsigned addr) {
    asm volatile("ldmatrix.sync.aligned.m8n8.x4.shared.b16 {%0,%1,%2,%3}, [%4];\n"
                 : "=r"(r[0]), "=r"(r[1]), "=r"(r[2]), "=r"(r[3])
                 : "r"(addr));
}

// ---------------- fused big TN GEMM (BK=32, 2-stage, static smem, ldmatrix) -----------
__global__ __launch_bounds__(256) void k_gemm_tn(
    const __nv_bfloat16* __restrict__ A, const __nv_bfloat16* __restrict__ B,
    float* __restrict__ C, int M) {
    __shared__ __nv_bfloat16 As[2][128 * GSTR];
    __shared__ __nv_bfloat16 Bs[2][128 * GSTR];
    int t = threadIdx.x;
    int mbase = blockIdx.x * 128, nbase = blockIdx.y * 128;
    int kb0 = blockIdx.z * GEMM_KBPC;
    int kb1 = min(TOTKB, kb0 + GEMM_KBPC);
    if (kb0 >= kb1) return;
    int niter = kb1 - kb0;
    unsigned sA = (unsigned)__cvta_generic_to_shared(&As[0][0]);
    unsigned sB = (unsigned)__cvta_generic_to_shared(&Bs[0][0]);
    int row_ = t >> 2, ch = t & 3;
    const __nv_bfloat16* gA0 = A + (size_t)min(mbase + row_, M - 1) * KP + ch * 8;
    const __nv_bfloat16* gA1 = A + (size_t)min(mbase + 64 + row_, M - 1) * KP + ch * 8;
    const __nv_bfloat16* gB0 = B + (size_t)(nbase + row_) * KP + ch * 8;
    const __nv_bfloat16* gB1 = B + (size_t)(nbase + 64 + row_) * KP + ch * 8;
    unsigned oA0 = sA + (row_ * GSTR + ch * 8) * 2, oA1 = oA0 + 64 * GSTR * 2;
    unsigned oB0 = sB + (row_ * GSTR + ch * 8) * 2, oB1 = oB0 + 64 * GSTR * 2;
    const unsigned BUFB = 128 * GSTR * 2;
    {
        long k0 = (long)kb0 * 32;
        cpa16(oA0, gA0 + k0); cpa16(oA1, gA1 + k0);
        cpa16(oB0, gB0 + k0); cpa16(oB1, gB1 + k0);
        asm volatile("cp.async.commit_group;\n");
    }
    float c[2][8][4];
#pragma unroll
    for (int mt = 0; mt < 2; mt++)
#pragma unroll
        for (int f = 0; f < 8; f++)
#pragma unroll
            for (int i = 0; i < 4; i++) c[mt][f][i] = 0.f;
    int w = t >> 5, lane = t & 31;
    int wm = (w & 3) * 32, wn = (w >> 2) * 64;
    unsigned aoff = sA + ((wm + (lane & 15)) * GSTR + (lane >> 4) * 8) * 2;
    unsigned boff = sB + ((wn + (lane & 7) + ((lane >> 4) << 3)) * GSTR + ((lane >> 3) & 1) * 8) * 2;
    for (int i = 0; i < niter; i++) {
        int cur = i & 1, nxt = cur ^ 1;
        if (i + 1 < niter) {
            long k = (long)(kb0 + i + 1) * 32;
            cpa16(oA0 + nxt * BUFB, gA0 + k); cpa16(oA1 + nxt * BUFB, gA1 + k);
            cpa16(oB0 + nxt * BUFB, gB0 + k); cpa16(oB1 + nxt * BUFB, gB1 + k);
        }
        asm volatile("cp.async.commit_group;\n");
        asm volatile("cp.async.wait_group 1;\n");
        __syncthreads();
        unsigned aC = aoff + cur * BUFB, bC = boff + cur * BUFB;
#pragma unroll
        for (int kk = 0; kk < 32; kk += 16) {
            unsigned A0[4], A1[4];
            ldsm4(A0, aC + kk * 2);
            ldsm4(A1, aC + (16 * GSTR + kk) * 2);
#pragma unroll
            for (int p = 0; p < 4; p++) {
                unsigned B4[4];
                ldsm4(B4, bC + (p * 16 * GSTR + kk) * 2);
                mma16816(c[0][2 * p], A0[0], A0[1], A0[2], A0[3], B4[0], B4[1]);
                mma16816(c[1][2 * p], A1[0], A1[1], A1[2], A1[3], B4[0], B4[1]);
                mma16816(c[0][2 * p + 1], A0[0], A0[1], A0[2], A0[3], B4[2], B4[3]);
                mma16816(c[1][2 * p + 1], A1[0], A1[1], A1[2], A1[3], B4[2], B4[3]);
            }
        }
        __syncthreads();
    }
    int gi = lane >> 2, qp = lane & 3;
#pragma unroll
    for (int mt = 0; mt < 2; mt++)
#pragma unroll
        for (int f = 0; f < 8; f++) {
            int gm0 = mbase + wm + mt * 16 + gi, gm1 = gm0 + 8;
            int gn = nbase + wn + f * 8 + qp * 2;
            if (gm0 < M) {
                atomicAdd(&C[gm0 * DN + gn], c[mt][f][0]);
                atomicAdd(&C[gm0 * DN + gn + 1], c[mt][f][1]);
            }
            if (gm1 < M) {
                atomicAdd(&C[gm1 * DN + gn], c[mt][f][2]);
                atomicAdd(&C[gm1 * DN + gn + 1], c[mt][f][3]);
            }
        }
}

// ---------------- gate GEMM (BK=32, K=256, static smem, highway fused, ldmatrix) ------
__global__ __launch_bounds__(256) void k_gate128(
    const __nv_bfloat16* __restrict__ Abf, const __nv_bfloat16* __restrict__ KwT,
    const float* __restrict__ bg, const float* __restrict__ G, const float* __restrict__ L1,
    float* __restrict__ H, __nv_bfloat16* __restrict__ Hbf) {
    __shared__ __nv_bfloat16 As[2][128 * GSTR];
    __shared__ __nv_bfloat16 Bs[2][128 * GSTR];
    int t = threadIdx.x;
    int mbase = blockIdx.x * 128, nbase = blockIdx.y * 128;
    unsigned sA = (unsigned)__cvta_generic_to_shared(&As[0][0]);
    unsigned sB = (unsigned)__cvta_generic_to_shared(&Bs[0][0]);
    int row_ = t >> 2, ch = t & 3;
    const __nv_bfloat16* gA0 = Abf + (size_t)min(mbase + row_, EN - 1) * DN + ch * 8;
    const __nv_bfloat16* gA1 = Abf + (size_t)min(mbase + 64 + row_, EN - 1) * DN + ch * 8;
    const __nv_bfloat16* gB0 = KwT + (size_t)(nbase + row_) * DN + ch * 8;
    const __nv_bfloat16* gB1 = KwT + (size_t)(nbase + 64 + row_) * DN + ch * 8;
    unsigned oA0 = sA + (row_ * GSTR + ch * 8) * 2, oA1 = oA0 + 64 * GSTR * 2;
    unsigned oB0 = sB + (row_ * GSTR + ch * 8) * 2, oB1 = oB0 + 64 * GSTR * 2;
    const unsigned BUFB = 128 * GSTR * 2;
    cpa16(oA0, gA0); cpa16(oA1, gA1);
    cpa16(oB0, gB0); cpa16(oB1, gB1);
    asm volatile("cp.async.commit_group;\n");
    float c[2][8][4];
#pragma unroll
    for (int mt = 0; mt < 2; mt++)
#pragma unroll
        for (int f = 0; f < 8; f++)
#pragma unroll
            for (int i = 0; i < 4; i++) c[mt][f][i] = 0.f;
    int w = t >> 5, lane = t & 31;
    int wm = (w & 3) * 32, wn = (w >> 2) * 64;
    unsigned aoff = sA + ((wm + (lane & 15)) * GSTR + (lane >> 4) * 8) * 2;
    unsigned boff = sB + ((wn + (lane & 7) + ((lane >> 4) << 3)) * GSTR + ((lane >> 3) & 1) * 8) * 2;
    const int NIT = DN / 32;
#pragma unroll
    for (int i = 0; i < NIT; i++) {
        int cur = i & 1, nxt = cur ^ 1;
        if (i + 1 < NIT) {
            int k = (i + 1) * 32;
            cpa16(oA0 + nxt * BUFB, gA0 + k); cpa16(oA1 + nxt * BUFB, gA1 + k);
            cpa16(oB0 + nxt * BUFB, gB0 + k); cpa16(oB1 + nxt * BUFB, gB1 + k);
        }
        asm volatile("cp.async.commit_group;\n");
        asm volatile("cp.async.wait_group 1;\n");
        __syncthreads();
        unsigned aC = aoff + cur * BUFB, bC = boff + cur * BUFB;
#pragma unroll
        for (int kk = 0; kk < 32; kk += 16) {
            unsigned A0[4], A1[4];
            ldsm4(A0, aC + kk * 2);
            ldsm4(A1, aC + (16 * GSTR + kk) * 2);
#pragma unroll
            for (int p = 0; p < 4; p++) {
                unsigned B4[4];
                ldsm4(B4, bC + (p * 16 * GSTR + kk) * 2);
                mma16816(c[0][2 * p], A0[0], A0[1], A0[2], A0[3], B4[0], B4[1]);
                mma16816(c[1][2 * p], A1[0], A1[1], A1[2], A1[3], B4[0], B4[1]);
                mma16816(c[0][2 * p + 1], A0[0], A0[1], A0[2], A0[3], B4[2], B4[3]);
                mma16816(c[1][2 * p + 1], A1[0], A1[1], A1[2], A1[3], B4[2], B4[3]);
            }
        }
        __syncthreads();
    }
    int gi = lane >> 2, qp = lane & 3;
#pragma unroll
    for (int mt = 0; mt < 2; mt++)
#pragma unroll
        for (int f = 0; f < 8; f++) {
            int gn = nbase + wn + f * 8 + qp * 2;
#pragma unroll
            for (int half = 0; half < 2; half++) {
                int gm = mbase + wm + mt * 16 + gi + half * 8;
                if (gm < EN) {
#pragma unroll
                    for (int j = 0; j < 2; j++) {
                        float z = c[mt][f][half * 2 + j] + bg[gn + j];
                        float tg = 1.f / (1.f + __expf(-z));
                        size_t off = (size_t)gm * DN + gn + j;
                        float hv = tg * G[off] + (1.f - tg) * L1[off];
                        H[off] = hv;
                        if (Hbf) Hbf[off] = __float2bfloat16(hv);
                    }
                }
            }
        }
}

// ------- small dense-att GEMM: dH = relu(coef @ valsT^T), K=512, + fused score -------
#define BM 64
#define BN 64
#define BKK 32
#define ASTR 40
__global__ __launch_bounds__(256) void k_gemm_small(const __nv_bfloat16* __restrict__ A,
                                                    const __nv_bfloat16* __restrict__ B,
                                                    float* __restrict__ C,
                                                    const float* __restrict__ wsp,
                                                    float* __restrict__ score) {
    __shared__ __nv_bfloat16 Asm[BM * ASTR];
    __shared__ __nv_bfloat16 Bsm[BN * ASTR];
    int t = threadIdx.x;
    int mbase = blockIdx.x * BM, nbase = blockIdx.y * BN;
    int w = t >> 5, lane = t & 31;
    int wm = (w & 3) * 16, wn = (w >> 2) * 32;
    int row = lane >> 2, qp = lane & 3;
    float c[4][4];
#pragma unroll
    for (int f = 0; f < 4; f++)
#pragma unroll
        for (int i = 0; i < 4; i++) c[f][i] = 0.f;
    for (int kb = 0; kb < 512; kb += BKK) {
#pragma unroll
        for (int i = 0; i < 8; i++) {
            int idx = t + i * 256;
            int m = idx >> 5, k = idx & 31;
            int gm = min(mbase + m, RN - 1);
            Asm[m * ASTR + k] = A[(size_t)gm * 512 + kb + k];
        }
#pragma unroll
        for (int i = 0; i < 8; i++) {
            int idx = t + i * 256;
            int n = idx >> 5, k = idx & 31;
            Bsm[n * ASTR + k] = B[(size_t)(nbase + n) * 512 + kb + k];
        }
        __syncthreads();
#pragma unroll
        for (int kk = 0; kk < BKK; kk += 16) {
            unsigned a0 = *(const unsigned*)&Asm[(wm + row) * ASTR + kk + qp * 2];
            unsigned a1 = *(const unsigned*)&Asm[(wm + row + 8) * ASTR + kk + qp * 2];
            unsigned a2 = *(const unsigned*)&Asm[(wm + row) * ASTR + kk + 8 + qp * 2];
            unsigned a3 = *(const unsigned*)&Asm[(wm + row + 8) * ASTR + kk + 8 + qp * 2];
#pragma unroll
            for (int f = 0; f < 4; f++) {
                unsigned b0 = *(const unsigned*)&Bsm[(wn + f * 8 + row) * ASTR + kk + qp * 2];
                unsigned b1 = *(const unsigned*)&Bsm[(wn + f * 8 + row) * ASTR + kk + 8 + qp * 2];
                mma16816(c[f], a0, a1, a2, a3, b0, b1);
            }
        }
        __syncthreads();
    }
    float p0 = 0.f, p1 = 0.f;
    int gm0 = mbase + wm + row, gm1 = gm0 + 8;
#pragma unroll
    for (int f = 0; f < 4; f++) {
        int gn = nbase + wn + f * 8 + qp * 2;
        float w0 = wsp[gn], w1v = wsp[gn + 1];
        float r00 = fmaxf(c[f][0], 0.f), r01 = fmaxf(c[f][1], 0.f);
        float r10 = fmaxf(c[f][2], 0.f), r11 = fmaxf(c[f][3], 0.f);
        if (gm0 < RN) {
            C[(size_t)gm0 * TWOD + gn] = r00;
            C[(size_t)gm0 * TWOD + gn + 1] = r01;
        }
        if (gm1 < RN) {
            C[(size_t)gm1 * TWOD + gn] = r10;
            C[(size_t)gm1 * TWOD + gn + 1] = r11;
        }
        p0 += r00 * w0 + r01 * w1v;
        p1 += r10 * w0 + r11 * w1v;
    }
    p0 += __shfl_xor_sync(0xffffffffu, p0, 1);
    p0 += __shfl_xor_sync(0xffffffffu, p0, 2);
    p1 += __shfl_xor_sync(0xffffffffu, p1, 1);
    p1 += __shfl_xor_sync(0xffffffffu, p1, 2);
    if (qp == 0) {
        if (gm0 < RN) atomicAdd(&score[gm0], p0);
        if (gm1 < RN) atomicAdd(&score[gm1], p1);
    }
}

// ---------------- small compute kernels ----------------
__global__ void k_norm(const float* __restrict__ LR, const float* __restrict__ cs,
                       float* __restrict__ dX) {
    int i = blockIdx.x * blockDim.x + threadIdx.x;
    if (i < RN * DN) {
        int r = i >> 8, d = i & 255;
        dX[r * TWOD + d] = LR[i] / cs[r];
        dX[r * TWOD + DN + d] = LR[RN * DN + i] / cs[RN + r];
    }
}
__device__ __forceinline__ float warpSum(float v) {
#pragma unroll
    for (int o = 16; o; o >>= 1) v += __shfl_xor_sync(0xffffffffu, v, o);
    return v;
}
__device__ __forceinline__ float warpMax(float v) {
#pragma unroll
    for (int o = 16; o; o >>= 1) v = fmaxf(v, __shfl_xor_sync(0xffffffffu, v, o));
    return v;
}
// fused: per-block v1/v2 = w2@w1, w3@w1 into smem, then per-warp f1/f2 dots
__global__ __launch_bounds__(256) void k_f2(
    const float* __restrict__ w1, const float* __restrict__ w2, const float* __restrict__ w3,
    const float* __restrict__ b2, const float* __restrict__ b3,
    const float* __restrict__ feats, float* __restrict__ f1, float* __restrict__ f2) {
    __shared__ float v1s[TWOD], v2s[TWOD];
    int tid = threadIdx.x;
    for (int i = tid; i < TWOD; i += 256) {
        float s1 = 0.f, s2 = 0.f;
        for (int h = 0; h < HIDN; h++) {
            float w = w1[h * TWOD + i];
            s1 += w2[h] * w;
            s2 += w3[h] * w;
        }
        v1s[i] = s1;
        v2s[i] = s2;
    }
    __syncthreads();
    int gw = (blockIdx.x * 256 + tid) >> 5;
    int lane = tid & 31;
    if (gw >= RN) return;
    float s1 = 0.f, s2 = 0.f;
    for (int i = lane; i < TWOD; i += 32) {
        float x = feats[gw * TWOD + i];
        s1 += x * v1s[i];
        s2 += x * v2s[i];
    }
    s1 = warpSum(s1);
    s2 = warpSum(s2);
    if (lane == 0) { f1[gw] = s1 + b2[0]; f2[gw] = s2 + b3[0]; }
}
// softmax coef row; also seeds score[r] = b_sp (consumed+accumulated by gemm_small)
__global__ __launch_bounds__(512) void k_coef(const float* __restrict__ f1,
                                              const float* __restrict__ f2,
                                              const float* __restrict__ adj,
                                              __nv_bfloat16* __restrict__ coefbf,
                                              const float* __restrict__ bsp,
                                              float* __restrict__ score) {
    int r = blockIdx.x;
    int tid = threadIdx.x;
    __shared__ float red[512];
    if (tid == 0) score[r] = bsp[0];
    float f1r = f1[r];
    float l = -INFINITY;
    if (tid < RN) {
        float a = adj[r * RN + tid];
        float x = a * (f1r + f2[tid]);
        l = x > 0.f ? x : SLOPE * x;
        if (!(a > 0.f)) l -= 1e9f;
    }
    red[tid] = l;
    __syncthreads();
    for (int s = 256; s > 0; s >>= 1) {
        if (tid < s) red[tid] = fmaxf(red[tid], red[tid + s]);
        __syncthreads();
    }
    float mx = red[0];
    __syncthreads();
    float e = (tid < RN) ? __expf(l - mx) : 0.f;
    red[tid] = e;
    __syncthreads();
    for (int s = 256; s > 0; s >>= 1) {
        if (tid < s) red[tid] += red[tid + s];
        __syncthreads();
    }
    float inv = 1.f / red[0];
    coefbf[(size_t)r * 512 + tid] = __float2bfloat16(e * inv);
}
// sparse attention: warp/row, bf16 gather (2-edge unrolled); fp32 out optional
__global__ __launch_bounds__(256) void k_satt(
    const __nv_bfloat16* __restrict__ Xsrc, const float* __restrict__ Xres,
    const float* __restrict__ score, const int* __restrict__ rptr,
    const int* __restrict__ perm, const int* __restrict__ rel, const int* __restrict__ col,
    float alpha, float* __restrict__ out, __nv_bfloat16* __restrict__ outbf) {
    int e = (blockIdx.x * blockDim.x + threadIdx.x) >> 5;
    int lane = threadIdx.x & 31;
    if (e >= EN) return;
    int s = rptr[e], t = rptr[e + 1];
    float acc[8];
#pragma unroll
    for (int i = 0; i < 8; i++) acc[i] = 0.f;
    if (t > s) {
        float m = -1e30f;
        for (int j = s + lane; j < t; j += 32) {
            float sc = score[rel[perm[j]]];
            float l = sc > 0.f ? sc : SLOPE * sc;
            m = fmaxf(m, l);
        }
        m = warpMax(m);
        float ssum = 0.f;
        for (int j = s + lane; j < t; j += 32) {
            float sc = score[rel[perm[j]]];
            float l = sc > 0.f ? sc : SLOPE * sc;
            ssum += __expf(l - m);
        }
        ssum = warpSum(ssum);
        float inv = 1.f / ssum;
        int j = s;
        for (; j + 1 < t; j += 2) {
            int id0 = perm[j], id1 = perm[j + 1];
            float sc0 = score[rel[id0]], sc1 = score[rel[id1]];
            float l0 = sc0 > 0.f ? sc0 : SLOPE * sc0;
            float l1 = sc1 > 0.f ? sc1 : SLOPE * sc1;
            float cf0 = __expf(l0 - m) * inv;
            float cf1 = __expf(l1 - m) * inv;
            uint4 v0 = ((const uint4*)(Xsrc + (size_t)col[id0] * DN))[lane];
            uint4 v1 = ((const uint4*)(Xsrc + (size_t)col[id1] * DN))[lane];
            float2 p;
            p = __bfloat1622float2(*(const __nv_bfloat162*)&v0.x);
            acc[0] += cf0 * p.x; acc[1] += cf0 * p.y;
            p = __bfloat1622float2(*(const __nv_bfloat162*)&v0.y);
            acc[2] += cf0 * p.x; acc[3] += cf0 * p.y;
            p = __bfloat1622float2(*(const __nv_bfloat162*)&v0.z);
            acc[4] += cf0 * p.x; acc[5] += cf0 * p.y;
            p = __bfloat1622float2(*(const __nv_bfloat162*)&v0.w);
            acc[6] += cf0 * p.x; acc[7] += cf0 * p.y;
            p = __bfloat1622float2(*(const __nv_bfloat162*)&v1.x);
            acc[0] += cf1 * p.x; acc[1] += cf1 * p.y;
            p = __bfloat1622float2(*(const __nv_bfloat162*)&v1.y);
            acc[2] += cf1 * p.x; acc[3] += cf1 * p.y;
            p = __bfloat1622float2(*(const __nv_bfloat162*)&v1.z);
            acc[4] += cf1 * p.x; acc[5] += cf1 * p.y;
            p = __bfloat1622float2(*(const __nv_bfloat162*)&v1.w);
            acc[6] += cf1 * p.x; acc[7] += cf1 * p.y;
        }
        if (j < t) {
            int id = perm[j];
            float sc = score[rel[id]];
            float l = sc > 0.f ? sc : SLOPE * sc;
            float cf = __expf(l - m) * inv;
            uint4 v = ((const uint4*)(Xsrc + (size_t)col[id] * DN))[lane];
            float2 p;
            p = __bfloat1622float2(*(const __nv_bfloat162*)&v.x);
            acc[0] += cf * p.x; acc[1] += cf * p.y;
            p = __bfloat1622float2(*(const __nv_bfloat162*)&v.y);
            acc[2] += cf * p.x; acc[3] += cf * p.y;
            p = __bfloat1622float2(*(const __nv_bfloat162*)&v.z);
            acc[4] += cf * p.x; acc[5] += cf * p.y;
            p = __bfloat1622float2(*(const __nv_bfloat162*)&v.w);
            acc[6] += cf * p.x; acc[7] += cf * p.y;
        }
    }
    size_t base = (size_t)e * DN;
    const float4* rr = (const float4*)(Xres + base);
    float4 r0 = rr[lane * 2], r1 = rr[lane * 2 + 1];
    float o[8];
    o[0] = r0.x + alpha * fmaxf(acc[0], 0.f);
    o[1] = r0.y + alpha * fmaxf(acc[1], 0.f);
    o[2] = r0.z + alpha * fmaxf(acc[2], 0.f);
    o[3] = r0.w + alpha * fmaxf(acc[3], 0.f);
    o[4] = r1.x + alpha * fmaxf(acc[4], 0.f);
    o[5] = r1.y + alpha * fmaxf(acc[5], 0.f);
    o[6] = r1.z + alpha * fmaxf(acc[6], 0.f);
    o[7] = r1.w + alpha * fmaxf(acc[7], 0.f);
    if (out) {
        ((float4*)(out + base))[lane * 2] = make_float4(o[0], o[1], o[2], o[3]);
        ((float4*)(out + base))[lane * 2 + 1] = make_float4(o[4], o[5], o[6], o[7]);
    }
    __nv_bfloat162 b0 = __floats2bfloat162_rn(o[0], o[1]);
    __nv_bfloat162 b1 = __floats2bfloat162_rn(o[2], o[3]);
    __nv_bfloat162 b2 = __floats2bfloat162_rn(o[4], o[5]);
    __nv_bfloat162 b3 = __floats2bfloat162_rn(o[6], o[7]);
    uint4 ob;
    ob.x = *(unsigned*)&b0; ob.y = *(unsigned*)&b1;
    ob.z = *(unsigned*)&b2; ob.w = *(unsigned*)&b3;
    ((uint4*)(outbf + base))[lane] = ob;
}
// GCN: warp/row, bf16 gather (2-edge unrolled)
__global__ __launch_bounds__(256) void k_gcn(
    const __nv_bfloat16* __restrict__ X, const float* __restrict__ w,
    const int* __restrict__ rptr, const int* __restrict__ perm,
    const float* __restrict__ val, const int* __restrict__ col, float* __restrict__ out) {
    int e = (blockIdx.x * blockDim.x + threadIdx.x) >> 5;
    int lane = threadIdx.x & 31;
    if (e >= EN) return;
    int s = rptr[e], t = rptr[e + 1];
    float acc[8];
#pragma unroll
    for (int i = 0; i < 8; i++) acc[i] = 0.f;
    int j = s;
    for (; j + 1 < t; j += 2) {
        int id0 = perm[j], id1 = perm[j + 1];
        float v0s = val[id0], v1s = val[id1];
        uint4 u0 = ((const uint4*)(X + (size_t)col[id0] * DN))[lane];
        uint4 u1 = ((const uint4*)(X + (size_t)col[id1] * DN))[lane];
        float2 p;
        p = __bfloat1622float2(*(const __nv_bfloat162*)&u0.x);
        acc[0] += v0s * p.x; acc[1] += v0s * p.y;
        p = __bfloat1622float2(*(const __nv_bfloat162*)&u0.y);
        acc[2] += v0s * p.x; acc[3] += v0s * p.y;
        p = __bfloat1622float2(*(const __nv_bfloat162*)&u0.z);
        acc[4] += v0s * p.x; acc[5] += v0s * p.y;
        p = __bfloat1622float2(*(const __nv_bfloat162*)&u0.w);
        acc[6] += v0s * p.x; acc[7] += v0s * p.y;
        p = __bfloat1622float2(*(const __nv_bfloat162*)&u1.x);
        acc[0] += v1s * p.x; acc[1] += v1s * p.y;
        p = __bfloat1622float2(*(const __nv_bfloat162*)&u1.y);
        acc[2] += v1s * p.x; acc[3] += v1s * p.y;
        p = __bfloat1622float2(*(const __nv_bfloat162*)&u1.z);
        acc[4] += v1s * p.x; acc[5] += v1s * p.y;
        p = __bfloat1622float2(*(const __nv_bfloat162*)&u1.w);
        acc[6] += v1s * p.x; acc[7] += v1s * p.y;
    }
    if (j < t) {
        int id = perm[j];
        float v = val[id];
        uint4 u = ((const uint4*)(X + (size_t)col[id] * DN))[lane];
        float2 p;
        p = __bfloat1622float2(*(const __nv_bfloat162*)&u.x);
        acc[0] += v * p.x; acc[1] += v * p.y;
        p = __bfloat1622float2(*(const __nv_bfloat162*)&u.y);
        acc[2] += v * p.x; acc[3] += v * p.y;
        p = __bfloat1622float2(*(const __nv_bfloat162*)&u.z);
        acc[4] += v * p.x; acc[5] += v * p.y;
        p = __bfloat1622float2(*(const __nv_bfloat162*)&u.w);
        acc[6] += v * p.x; acc[7] += v * p.y;
    }
    size_t base = (size_t)e * DN;
    int d = lane * 8;
    float4 o0 = make_float4(fmaxf(acc[0] * w[d], 0.f), fmaxf(acc[1] * w[d + 1], 0.f),
                            fmaxf(acc[2] * w[d + 2], 0.f), fmaxf(acc[3] * w[d + 3], 0.f));
    float4 o1 = make_float4(fmaxf(acc[4] * w[d + 4], 0.f), fmaxf(acc[5] * w[d + 5], 0.f),
                            fmaxf(acc[6] * w[d + 6], 0.f), fmaxf(acc[7] * w[d + 7], 0.f));
    ((float4*)(out + base))[lane * 2] = o0;
    ((float4*)(out + base))[lane * 2 + 1] = o1;
}

// ---------------- host ----------------
extern "C" void kernel_launch(void* const* d_in, const int* in_sizes, int n_in,
                              void* d_out, int out_size) {
    const float* X0 = (const float*)d_in[0];
    const float* head_r = (const float*)d_in[1];
    const float* tail_r = (const float*)d_in[2];
    const float* dual_A = (const float*)d_in[3];
    const int* erow = (const int*)d_in[4];
    const int* ecol = (const int*)d_in[5];
    const int* erel = (const int*)d_in[6];
    const int* mrow = (const int*)d_in[7];
    const int* mcol = (const int*)d_in[8];
    const float* mval = (const float*)d_in[9];
    const float* w_self1 = (const float*)d_in[10];
    const float* w_self2 = (const float*)d_in[11];
    const float* b_self2 = (const float*)d_in[12];
    const float* w_self3 = (const float*)d_in[13];
    const float* b_self3 = (const float*)d_in[14];
    const float* w_sp1 = (const float*)d_in[15];
    const float* b_sp1 = (const float*)d_in[16];
    const float* w_dual1 = (const float*)d_in[17];
    const float* w_dual2 = (const float*)d_in[18];
    const float* b_dual2 = (const float*)d_in[19];
    const float* w_dual3 = (const float*)d_in[20];
    const float* b_dual3 = (const float*)d_in[21];
    const float* w_sp2 = (const float*)d_in[22];
    const float* b_sp2 = (const float*)d_in[23];
    const float* w_gcn1 = (const float*)d_in[24];
    const float* w_gcn2 = (const float*)d_in[25];
    const float* k_hw1 = (const float*)d_in[26];
    const float* bg_hw1 = (const float*)d_in[27];
    const float* k_hw2 = (const float*)d_in[28];
    const float* bg_hw2 = (const float*)d_in[29];
    float* outp = (float*)d_out;

    float *pX2, *gb, *h1, *LR, *cs, *dX, *dH1, *dH2, *f1, *f2, *score;
    __nv_bfloat16 *Xbf, *Xbf2, *Xbf3, *HT, *XT, *KwT1, *KwT2, *coefbf, *valsT;
    int *cntE, *cntM, *curE, *curM, *erptr, *eperm, *mrptr, *mperm;
    cudaGetSymbolAddress((void**)&pX2, g_pX2);
    cudaGetSymbolAddress((void**)&gb, g_gb);
    cudaGetSymbolAddress((void**)&h1, g_h1);
    cudaGetSymbolAddress((void**)&Xbf, g_Xbf);
    cudaGetSymbolAddress((void**)&Xbf2, g_Xbf2);
    cudaGetSymbolAddress((void**)&Xbf3, g_Xbf3);
    cudaGetSymbolAddress((void**)&HT, g_HT);
    cudaGetSymbolAddress((void**)&XT, g_XT);
    cudaGetSymbolAddress((void**)&KwT1, g_KwT1);
    cudaGetSymbolAddress((void**)&KwT2, g_KwT2);
    cudaGetSymbolAddress((void**)&coefbf, g_coefbf);
    cudaGetSymbolAddress((void**)&valsT, g_valsT);
    cudaGetSymbolAddress((void**)&LR, g_LR);
    cudaGetSymbolAddress((void**)&cs, g_cs);
    cudaGetSymbolAddress((void**)&dX, g_dX);
    cudaGetSymbolAddress((void**)&dH1, g_dH1);
    cudaGetSymbolAddress((void**)&dH2, g_dH2);
    cudaGetSymbolAddress((void**)&f1, g_f1);
    cudaGetSymbolAddress((void**)&f2, g_f2);
    cudaGetSymbolAddress((void**)&score, g_score);
    cudaGetSymbolAddress((void**)&cntE, g_cntE);
    cudaGetSymbolAddress((void**)&cntM, g_cntM);
    cudaGetSymbolAddress((void**)&curE, g_curE);
    cudaGetSymbolAddress((void**)&curM, g_curM);
    cudaGetSymbolAddress((void**)&erptr, g_erptr);
    cudaGetSymbolAddress((void**)&eperm, g_eperm);
    cudaGetSymbolAddress((void**)&mrptr, g_mrptr);
    cudaGetSymbolAddress((void**)&mperm, g_mperm);

    const int T = 256;
    int gRD = (RN * DN + T - 1) / T;
    int gNE = (NEDGE + T - 1) / T;
    int gFW = (RN * 32 + T - 1) / T;   // k_f2 blocks (warp per relation)
    int gRow = (EN * 32 + T - 1) / T;
    dim3 gT(KP / 32, 16);
    dim3 gTX9(KP / 32, 9);
    dim3 gPX(KP / 32, 9);
    dim3 gg(8, 2, GEMM_Z);
    dim3 gGate((EN + 127) / 128, DN / 128);
    dim3 gSm((RN + BM - 1) / BM, TWOD / BN);
    dim3 gTr(16, 16);

    // setup; launch 4 = fused big GEMM (ncu capture slot)
    k_prepX_init<<<gPX, T>>>(X0, XT, Xbf, LR, cs, cntE, cntM, k_hw1, k_hw2, KwT1, KwT2);
    k_prepT<<<gT, T>>>(head_r, HT, cs, RN);
    k_prepT<<<gT, T>>>(tail_r, HT + (size_t)500 * KP, cs + 500, RN);
    k_gemm_tn<<<gg, T>>>(HT, XT, LR, 1000);
    k_norm<<<gRD, T>>>(LR, cs, dX);
    // CSR builds (fused)
    k_hist2<<<gNE, T>>>(erow, mrow, cntE, cntM);
    k_scan2<<<1, 1024>>>(cntE, erptr, curE, cntM, mrptr, curM);
    k_scatter2<<<gNE, T>>>(erow, curE, eperm, mrow, curM, mperm);
    // dense att 1 (v fused into f; score fused into gemm_small)
    k_f2<<<gFW, T>>>(w_self1, w_self2, w_self3, b_self2, b_self3, dX, f1, f2);
    k_coef<<<RN, 512>>>(f1, f2, dual_A, coefbf, b_sp1, score);
    k_transpT<<<gTr, T>>>(dX, valsT);
    k_gemm_small<<<gSm, T>>>(coefbf, valsT, dH1, w_sp1, score);
    // sparse att 1
    k_satt<<<gRow, T>>>(Xbf, X0, score, erptr, eperm, erel, ecol, 0.1f, (float*)0, Xbf2);
    // compute_r(pX1)
    k_transpTbf<<<gTX9, T>>>(Xbf2, XT, LR);
    k_gemm_tn<<<gg, T>>>(HT, XT, LR, 1000);
    k_norm<<<gRD, T>>>(LR, cs, dX);
    // dense att 2
    k_f2<<<gFW, T>>>(w_dual1, w_dual2, w_dual3, b_dual2, b_dual3, dX, f1, f2);
    k_coef<<<RN, 512>>>(f1, f2, dual_A, coefbf, b_sp2, score);
    k_transpT<<<gTr, T>>>(dH1, valsT);
    k_gemm_small<<<gSm, T>>>(coefbf, valsT, dH2, w_sp2, score);
    // sparse att 2
    k_satt<<<gRow, T>>>(Xbf2, X0, score, erptr, eperm, erel, ecol, 0.3f, pX2, Xbf3);
    // GCN + highway
    k_gcn<<<gRow, T>>>(Xbf3, w_gcn1, mrptr, mperm, mval, mcol, gb);
    k_gate128<<<gGate, T>>>(Xbf3, KwT1, bg_hw1, gb, pX2, h1, Xbf);
    k_gcn<<<gRow, T>>>(Xbf, w_gcn2, mrptr, mperm, mval, mcol, gb);
    k_gate128<<<gGate, T>>>(Xbf, KwT2, bg_hw2, gb, h1, outp, (__nv_bfloat16*)0);
}

// round 14
// speedup vs baseline: 1.4240x; 1.4240x over previous
#include <cuda_runtime.h>
#include <cuda_bf16.h>
#include <math.h>

#define EN 50000
#define RN 500
#define DN 256
#define NEDGE 500000
#define TWOD 512
#define HIDN 128
#define SLOPE 0.01f
#define KP 50048
#define TOTKB (KP / 32)
#define GEMM_Z 37
#define GEMM_KBPC 43
#define GSTR 40

// ---------------- static scratch ----------------
__device__ float g_pX2[EN * DN];
__device__ float g_gb[EN * DN];
__device__ float g_h1[EN * DN];
__device__ __nv_bfloat16 g_Xbf[EN * DN];
__device__ __nv_bfloat16 g_Xbf2[EN * DN];
__device__ __nv_bfloat16 g_Xbf3[EN * DN];
__device__ __nv_bfloat16 g_HT[1000 * KP];
__device__ __nv_bfloat16 g_XT[DN * KP];
__device__ __nv_bfloat16 g_KwT1[DN * DN];
__device__ __nv_bfloat16 g_KwT2[DN * DN];
__device__ __nv_bfloat16 g_coefbf[512 * 512];
__device__ __nv_bfloat16 g_valsT[512 * 512];
__device__ float g_LR[1000 * DN];
__device__ float g_cs[1000];
__device__ float g_dX[RN * TWOD];
__device__ float g_dH1[RN * TWOD];
__device__ float g_dH2[RN * TWOD];
__device__ float g_f1[RN];
__device__ float g_f2[RN];
__device__ float g_score[RN];
__device__ int g_cntE[EN];
__device__ int g_cntM[EN];
__device__ int g_curE[EN];
__device__ int g_curM[EN];
__device__ int g_erptr[EN + 1];
__device__ int g_eperm[NEDGE];
__device__ int g_mrptr[EN + 1];
__device__ int g_mperm[NEDGE];

// ---------------- fused X-transpose + global init + Kw prep ----------------
__global__ void k_prepX_init(const float* __restrict__ In, __nv_bfloat16* __restrict__ OutT,
                             __nv_bfloat16* __restrict__ Rowbf, float* __restrict__ LR,
                             float* __restrict__ cs, int* cE, int* cM,
                             const float* __restrict__ K1, const float* __restrict__ K2,
                             __nv_bfloat16* __restrict__ T1, __nv_bfloat16* __restrict__ T2) {
    if (blockIdx.y == 8) {
        int i = blockIdx.x * blockDim.x + threadIdx.x;
        if (i < 1000 * DN) LR[i] = 0.f;
        if (i < 1000) cs[i] = 0.f;
        if (i < EN) { cE[i] = 0; cM[i] = 0; }
        if (i < DN * DN) {
            int n = i >> 8, k = i & 255;
            T1[i] = __float2bfloat16(K1[k * DN + n]);
            T2[i] = __float2bfloat16(K2[k * DN + n]);
        }
        return;
    }
    __shared__ float tile[32][33];
    int e0 = blockIdx.x * 32, r0 = blockIdx.y * 32;
    int tx = threadIdx.x & 31, ty = threadIdx.x >> 5;
#pragma unroll
    for (int j = 0; j < 4; j++) {
        int e = e0 + ty + j * 8, r = r0 + tx;
        float v = (e < EN) ? In[(size_t)e * DN + r] : 0.f;
        tile[ty + j * 8][tx] = v;
        if (e < EN) Rowbf[(size_t)e * DN + r] = __float2bfloat16(v);
    }
    __syncthreads();
#pragma unroll
    for (int j = 0; j < 4; j++) {
        int r = r0 + ty + j * 8, e = e0 + tx;
        OutT[(size_t)r * KP + e] = __float2bfloat16(tile[tx][ty + j * 8]);
    }
}

// transpose In [EN][R] fp32 -> OutT [R][KP] bf16 (pad zero); optional colsum
__global__ void k_prepT(const float* __restrict__ In, __nv_bfloat16* __restrict__ OutT,
                        float* __restrict__ colsum, int R) {
    __shared__ float tile[32][33];
    int e0 = blockIdx.x * 32, r0 = blockIdx.y * 32;
    int tx = threadIdx.x & 31, ty = threadIdx.x >> 5;
#pragma unroll
    for (int j = 0; j < 4; j++) {
        int e = e0 + ty + j * 8, r = r0 + tx;
        tile[ty + j * 8][tx] = (e < EN && r < R) ? In[(size_t)e * R + r] : 0.f;
    }
    __syncthreads();
#pragma unroll
    for (int j = 0; j < 4; j++) {
        int r = r0 + ty + j * 8, e = e0 + tx;
        if (r < R) OutT[(size_t)r * KP + e] = __float2bfloat16(tile[tx][ty + j * 8]);
    }
    if (colsum && ty == 0 && r0 + tx < R) {
        float s = 0.f;
#pragma unroll
        for (int e = 0; e < 32; e++) s += tile[e][tx];
        atomicAdd(&colsum[r0 + tx], s);
    }
}

// transpose bf16 [EN][DN] -> [DN][KP] bf16 (pad zero); extra y-slice zeros LR
__global__ void k_transpTbf(const __nv_bfloat16* __restrict__ In,
                            __nv_bfloat16* __restrict__ OutT, float* __restrict__ LR) {
    if (blockIdx.y == 8) {
        int i = blockIdx.x * blockDim.x + threadIdx.x;
        if (i < 1000 * DN) LR[i] = 0.f;
        return;
    }
    __shared__ __nv_bfloat16 tile[32][33];
    int e0 = blockIdx.x * 32, r0 = blockIdx.y * 32;
    int tx = threadIdx.x & 31, ty = threadIdx.x >> 5;
#pragma unroll
    for (int j = 0; j < 4; j++) {
        int e = e0 + ty + j * 8, r = r0 + tx;
        tile[ty + j * 8][tx] = (e < EN) ? In[(size_t)e * DN + r] : __float2bfloat16(0.f);
    }
    __syncthreads();
#pragma unroll
    for (int j = 0; j < 4; j++) {
        int r = r0 + ty + j * 8, e = e0 + tx;
        OutT[(size_t)r * KP + e] = tile[tx][ty + j * 8];
    }
}

// vals [RN][512] fp32 -> valsT [512][512] bf16
__global__ void k_transpT(const float* __restrict__ in, __nv_bfloat16* __restrict__ out) {
    __shared__ float tile[32][33];
    int j0 = blockIdx.x * 32, d0 = blockIdx.y * 32;
    int tx = threadIdx.x & 31, ty = threadIdx.x >> 5;
#pragma unroll
    for (int jj = 0; jj < 4; jj++) {
        int j = j0 + ty + jj * 8;
        tile[ty + jj * 8][tx] = (j < RN) ? in[(size_t)j * TWOD + d0 + tx] : 0.f;
    }
    __syncthreads();
#pragma unroll
    for (int jj = 0; jj < 4; jj++) {
        int d = d0 + ty + jj * 8;
        out[(size_t)d * 512 + j0 + tx] = __float2bfloat16(tile[tx][ty + jj * 8]);
    }
}

// ---------------- CSR build (both graphs fused) ----------------
__global__ void k_hist2(const int* __restrict__ er, const int* __restrict__ mr, int* cE,
                        int* cM) {
    int i = blockIdx.x * blockDim.x + threadIdx.x;
    if (i < NEDGE) {
        atomicAdd(&cE[er[i]], 1);
        atomicAdd(&cM[mr[i]], 1);
    }
}
__global__ void k_scan2(const int* __restrict__ cA, int* __restrict__ pA, int* __restrict__ uA,
                        const int* __restrict__ cB, int* __restrict__ pB, int* __restrict__ uB) {
    __shared__ int wsum[32];
    __shared__ int s_run;
    int tid = threadIdx.x, lane = tid & 31, w = tid >> 5;
    for (int g = 0; g < 2; g++) {
        const int* cnt = g ? cB : cA;
        int* ptr = g ? pB : pA;
        int* cur = g ? uB : uA;
        if (tid == 0) s_run = 0;
        __syncthreads();
        for (int base = 0; base < EN; base += 1024) {
            int i = base + tid;
            int v = (i < EN) ? cnt[i] : 0;
            int x = v;
#pragma unroll
            for (int o = 1; o < 32; o <<= 1) {
                int y = __shfl_up_sync(0xffffffffu, x, o);
                if (lane >= o) x += y;
            }
            if (lane == 31) wsum[w] = x;
            __syncthreads();
            if (w == 0) {
                int s = wsum[lane];
#pragma unroll
                for (int o = 1; o < 32; o <<= 1) {
                    int y = __shfl_up_sync(0xffffffffu, s, o);
                    if (lane >= o) s += y;
                }
                wsum[lane] = s;
            }
            __syncthreads();
            int excl = s_run + x - v + (w ? wsum[w - 1] : 0);
            if (i < EN) { ptr[i] = excl; cur[i] = excl; }
            __syncthreads();
            if (tid == 1023) s_run += wsum[31];
            __syncthreads();
        }
        if (tid == 0) ptr[EN] = s_run;
        __syncthreads();
    }
}
__global__ void k_scatter2(const int* __restrict__ er, int* uE, int* __restrict__ pe,
                           const int* __restrict__ mr, int* uM, int* __restrict__ pm) {
    int i = blockIdx.x * blockDim.x + threadIdx.x;
    if (i < NEDGE) {
        pe[atomicAdd(&uE[er[i]], 1)] = i;
        pm[atomicAdd(&uM[mr[i]], 1)] = i;
    }
}

// ---------------- mma helpers ----------------
__device__ __forceinline__ void mma16816(float* c, unsigned a0, unsigned a1, unsigned a2,
                                         unsigned a3, unsigned b0, unsigned b1) {
    asm volatile(
        "mma.sync.aligned.m16n8k16.row.col.f32.bf16.bf16.f32 "
        "{%0,%1,%2,%3},{%4,%5,%6,%7},{%8,%9},{%0,%1,%2,%3};\n"
        : "+f"(c[0]), "+f"(c[1]), "+f"(c[2]), "+f"(c[3])
        : "r"(a0), "r"(a1), "r"(a2), "r"(a3), "r"(b0), "r"(b1));
}
__device__ __forceinline__ void cpa16(unsigned s, const void* g) {
    asm volatile("cp.async.cg.shared.global [%0], [%1], 16;\n" ::"r"(s), "l"(g));
}
__device__ __forceinline__ void ldsm4(unsigned* r, unsigned addr) {
    asm volatile("ldmatrix.sync.aligned.m8n8.x4.shared.b16 {%0,%1,%2,%3}, [%4];\n"
                 : "=r"(r[0]), "=r"(r[1]), "=r"(r[2]), "=r"(r[3])
                 : "r"(addr));
}

// ---------------- fused big TN GEMM (BK=32, 2-stage, static smem, ldmatrix) -----------
__global__ __launch_bounds__(256) void k_gemm_tn(
    const __nv_bfloat16* __restrict__ A, const __nv_bfloat16* __restrict__ B,
    float* __restrict__ C, int M) {
    __shared__ __nv_bfloat16 As[2][128 * GSTR];
    __shared__ __nv_bfloat16 Bs[2][128 * GSTR];
    int t = threadIdx.x;
    int mbase = blockIdx.x * 128, nbase = blockIdx.y * 128;
    int kb0 = blockIdx.z * GEMM_KBPC;
    int kb1 = min(TOTKB, kb0 + GEMM_KBPC);
    if (kb0 >= kb1) return;
    int niter = kb1 - kb0;
    unsigned sA = (unsigned)__cvta_generic_to_shared(&As[0][0]);
    unsigned sB = (unsigned)__cvta_generic_to_shared(&Bs[0][0]);
    int row_ = t >> 2, ch = t & 3;
    const __nv_bfloat16* gA0 = A + (size_t)min(mbase + row_, M - 1) * KP + ch * 8;
    const __nv_bfloat16* gA1 = A + (size_t)min(mbase + 64 + row_, M - 1) * KP + ch * 8;
    const __nv_bfloat16* gB0 = B + (size_t)(nbase + row_) * KP + ch * 8;
    const __nv_bfloat16* gB1 = B + (size_t)(nbase + 64 + row_) * KP + ch * 8;
    unsigned oA0 = sA + (row_ * GSTR + ch * 8) * 2, oA1 = oA0 + 64 * GSTR * 2;
    unsigned oB0 = sB + (row_ * GSTR + ch * 8) * 2, oB1 = oB0 + 64 * GSTR * 2;
    const unsigned BUFB = 128 * GSTR * 2;
    {
        long k0 = (long)kb0 * 32;
        cpa16(oA0, gA0 + k0); cpa16(oA1, gA1 + k0);
        cpa16(oB0, gB0 + k0); cpa16(oB1, gB1 + k0);
        asm volatile("cp.async.commit_group;\n");
    }
    float c[2][8][4];
#pragma unroll
    for (int mt = 0; mt < 2; mt++)
#pragma unroll
        for (int f = 0; f < 8; f++)
#pragma unroll
            for (int i = 0; i < 4; i++) c[mt][f][i] = 0.f;
    int w = t >> 5, lane = t & 31;
    int wm = (w & 3) * 32, wn = (w >> 2) * 64;
    unsigned aoff = sA + ((wm + (lane & 15)) * GSTR + (lane >> 4) * 8) * 2;
    unsigned boff = sB + ((wn + (lane & 7) + ((lane >> 4) << 3)) * GSTR + ((lane >> 3) & 1) * 8) * 2;
    for (int i = 0; i < niter; i++) {
        int cur = i & 1, nxt = cur ^ 1;
        if (i + 1 < niter) {
            long k = (long)(kb0 + i + 1) * 32;
            cpa16(oA0 + nxt * BUFB, gA0 + k); cpa16(oA1 + nxt * BUFB, gA1 + k);
            cpa16(oB0 + nxt * BUFB, gB0 + k); cpa16(oB1 + nxt * BUFB, gB1 + k);
        }
        asm volatile("cp.async.commit_group;\n");
        asm volatile("cp.async.wait_group 1;\n");
        __syncthreads();
        unsigned aC = aoff + cur * BUFB, bC = boff + cur * BUFB;
#pragma unroll
        for (int kk = 0; kk < 32; kk += 16) {
            unsigned A0[4], A1[4];
            ldsm4(A0, aC + kk * 2);
            ldsm4(A1, aC + (16 * GSTR + kk) * 2);
#pragma unroll
            for (int p = 0; p < 4; p++) {
                unsigned B4[4];
                ldsm4(B4, bC + (p * 16 * GSTR + kk) * 2);
                mma16816(c[0][2 * p], A0[0], A0[1], A0[2], A0[3], B4[0], B4[1]);
                mma16816(c[1][2 * p], A1[0], A1[1], A1[2], A1[3], B4[0], B4[1]);
                mma16816(c[0][2 * p + 1], A0[0], A0[1], A0[2], A0[3], B4[2], B4[3]);
                mma16816(c[1][2 * p + 1], A1[0], A1[1], A1[2], A1[3], B4[2], B4[3]);
            }
        }
        __syncthreads();
    }
    int gi = lane >> 2, qp = lane & 3;
#pragma unroll
    for (int mt = 0; mt < 2; mt++)
#pragma unroll
        for (int f = 0; f < 8; f++) {
            int gm0 = mbase + wm + mt * 16 + gi, gm1 = gm0 + 8;
            int gn = nbase + wn + f * 8 + qp * 2;
            if (gm0 < M) {
                atomicAdd(&C[gm0 * DN + gn], c[mt][f][0]);
                atomicAdd(&C[gm0 * DN + gn + 1], c[mt][f][1]);
            }
            if (gm1 < M) {
                atomicAdd(&C[gm1 * DN + gn], c[mt][f][2]);
                atomicAdd(&C[gm1 * DN + gn + 1], c[mt][f][3]);
            }
        }
}

// ---------------- gate GEMM (BK=32, K=256, static smem, highway fused, ldmatrix) ------
__global__ __launch_bounds__(256) void k_gate128(
    const __nv_bfloat16* __restrict__ Abf, const __nv_bfloat16* __restrict__ KwT,
    const float* __restrict__ bg, const float* __restrict__ G, const float* __restrict__ L1,
    float* __restrict__ H, __nv_bfloat16* __restrict__ Hbf) {
    __shared__ __nv_bfloat16 As[2][128 * GSTR];
    __shared__ __nv_bfloat16 Bs[2][128 * GSTR];
    int t = threadIdx.x;
    int mbase = blockIdx.x * 128, nbase = blockIdx.y * 128;
    unsigned sA = (unsigned)__cvta_generic_to_shared(&As[0][0]);
    unsigned sB = (unsigned)__cvta_generic_to_shared(&Bs[0][0]);
    int row_ = t >> 2, ch = t & 3;
    const __nv_bfloat16* gA0 = Abf + (size_t)min(mbase + row_, EN - 1) * DN + ch * 8;
    const __nv_bfloat16* gA1 = Abf + (size_t)min(mbase + 64 + row_, EN - 1) * DN + ch * 8;
    const __nv_bfloat16* gB0 = KwT + (size_t)(nbase + row_) * DN + ch * 8;
    const __nv_bfloat16* gB1 = KwT + (size_t)(nbase + 64 + row_) * DN + ch * 8;
    unsigned oA0 = sA + (row_ * GSTR + ch * 8) * 2, oA1 = oA0 + 64 * GSTR * 2;
    unsigned oB0 = sB + (row_ * GSTR + ch * 8) * 2, oB1 = oB0 + 64 * GSTR * 2;
    const unsigned BUFB = 128 * GSTR * 2;
    cpa16(oA0, gA0); cpa16(oA1, gA1);
    cpa16(oB0, gB0); cpa16(oB1, gB1);
    asm volatile("cp.async.commit_group;\n");
    float c[2][8][4];
#pragma unroll
    for (int mt = 0; mt < 2; mt++)
#pragma unroll
        for (int f = 0; f < 8; f++)
#pragma unroll
            for (int i = 0; i < 4; i++) c[mt][f][i] = 0.f;
    int w = t >> 5, lane = t & 31;
    int wm = (w & 3) * 32, wn = (w >> 2) * 64;
    unsigned aoff = sA + ((wm + (lane & 15)) * GSTR + (lane >> 4) * 8) * 2;
    unsigned boff = sB + ((wn + (lane & 7) + ((lane >> 4) << 3)) * GSTR + ((lane >> 3) & 1) * 8) * 2;
    const int NIT = DN / 32;
#pragma unroll
    for (int i = 0; i < NIT; i++) {
        int cur = i & 1, nxt = cur ^ 1;
        if (i + 1 < NIT) {
            int k = (i + 1) * 32;
            cpa16(oA0 + nxt * BUFB, gA0 + k); cpa16(oA1 + nxt * BUFB, gA1 + k);
            cpa16(oB0 + nxt * BUFB, gB0 + k); cpa16(oB1 + nxt * BUFB, gB1 + k);
        }
        asm volatile("cp.async.commit_group;\n");
        asm volatile("cp.async.wait_group 1;\n");
        __syncthreads();
        unsigned aC = aoff + cur * BUFB, bC = boff + cur * BUFB;
#pragma unroll
        for (int kk = 0; kk < 32; kk += 16) {
            unsigned A0[4], A1[4];
            ldsm4(A0, aC + kk * 2);
            ldsm4(A1, aC + (16 * GSTR + kk) * 2);
#pragma unroll
            for (int p = 0; p < 4; p++) {
                unsigned B4[4];
                ldsm4(B4, bC + (p * 16 * GSTR + kk) * 2);
                mma16816(c[0][2 * p], A0[0], A0[1], A0[2], A0[3], B4[0], B4[1]);
                mma16816(c[1][2 * p], A1[0], A1[1], A1[2], A1[3], B4[0], B4[1]);
                mma16816(c[0][2 * p + 1], A0[0], A0[1], A0[2], A0[3], B4[2], B4[3]);
                mma16816(c[1][2 * p + 1], A1[0], A1[1], A1[2], A1[3], B4[2], B4[3]);
            }
        }
        __syncthreads();
    }
    int gi = lane >> 2, qp = lane & 3;
#pragma unroll
    for (int mt = 0; mt < 2; mt++)
#pragma unroll
        for (int f = 0; f < 8; f++) {
            int gn = nbase + wn + f * 8 + qp * 2;
#pragma unroll
            for (int half = 0; half < 2; half++) {
                int gm = mbase + wm + mt * 16 + gi + half * 8;
                if (gm < EN) {
#pragma unroll
                    for (int j = 0; j < 2; j++) {
                        float z = c[mt][f][half * 2 + j] + bg[gn + j];
                        float tg = 1.f / (1.f + __expf(-z));
                        size_t off = (size_t)gm * DN + gn + j;
                        float hv = tg * G[off] + (1.f - tg) * L1[off];
                        H[off] = hv;
                        if (Hbf) Hbf[off] = __float2bfloat16(hv);
                    }
                }
            }
        }
}

// ------- small dense-att GEMM: dH = relu(coef @ valsT^T), K=512, + fused score -------
#define BM 64
#define BN 64
#define BKK 32
#define ASTR 40
__global__ __launch_bounds__(256) void k_gemm_small(const __nv_bfloat16* __restrict__ A,
                                                    const __nv_bfloat16* __restrict__ B,
                                                    float* __restrict__ C,
                                                    const float* __restrict__ wsp,
                                                    float* __restrict__ score) {
    __shared__ __nv_bfloat16 Asm[BM * ASTR];
    __shared__ __nv_bfloat16 Bsm[BN * ASTR];
    int t = threadIdx.x;
    int mbase = blockIdx.x * BM, nbase = blockIdx.y * BN;
    int w = t >> 5, lane = t & 31;
    int wm = (w & 3) * 16, wn = (w >> 2) * 32;
    int row = lane >> 2, qp = lane & 3;
    float c[4][4];
#pragma unroll
    for (int f = 0; f < 4; f++)
#pragma unroll
        for (int i = 0; i < 4; i++) c[f][i] = 0.f;
    for (int kb = 0; kb < 512; kb += BKK) {
#pragma unroll
        for (int i = 0; i < 8; i++) {
            int idx = t + i * 256;
            int m = idx >> 5, k = idx & 31;
            int gm = min(mbase + m, RN - 1);
            Asm[m * ASTR + k] = A[(size_t)gm * 512 + kb + k];
        }
#pragma unroll
        for (int i = 0; i < 8; i++) {
            int idx = t + i * 256;
            int n = idx >> 5, k = idx & 31;
            Bsm[n * ASTR + k] = B[(size_t)(nbase + n) * 512 + kb + k];
        }
        __syncthreads();
#pragma unroll
        for (int kk = 0; kk < BKK; kk += 16) {
            unsigned a0 = *(const unsigned*)&Asm[(wm + row) * ASTR + kk + qp * 2];
            unsigned a1 = *(const unsigned*)&Asm[(wm + row + 8) * ASTR + kk + qp * 2];
            unsigned a2 = *(const unsigned*)&Asm[(wm + row) * ASTR + kk + 8 + qp * 2];
            unsigned a3 = *(const unsigned*)&Asm[(wm + row + 8) * ASTR + kk + 8 + qp * 2];
#pragma unroll
            for (int f = 0; f < 4; f++) {
                unsigned b0 = *(const unsigned*)&Bsm[(wn + f * 8 + row) * ASTR + kk + qp * 2];
                unsigned b1 = *(const unsigned*)&Bsm[(wn + f * 8 + row) * ASTR + kk + 8 + qp * 2];
                mma16816(c[f], a0, a1, a2, a3, b0, b1);
            }
        }
        __syncthreads();
    }
    float p0 = 0.f, p1 = 0.f;
    int gm0 = mbase + wm + row, gm1 = gm0 + 8;
#pragma unroll
    for (int f = 0; f < 4; f++) {
        int gn = nbase + wn + f * 8 + qp * 2;
        float w0 = wsp[gn], w1v = wsp[gn + 1];
        float r00 = fmaxf(c[f][0], 0.f), r01 = fmaxf(c[f][1], 0.f);
        float r10 = fmaxf(c[f][2], 0.f), r11 = fmaxf(c[f][3], 0.f);
        if (gm0 < RN) {
            C[(size_t)gm0 * TWOD + gn] = r00;
            C[(size_t)gm0 * TWOD + gn + 1] = r01;
        }
        if (gm1 < RN) {
            C[(size_t)gm1 * TWOD + gn] = r10;
            C[(size_t)gm1 * TWOD + gn + 1] = r11;
        }
        p0 += r00 * w0 + r01 * w1v;
        p1 += r10 * w0 + r11 * w1v;
    }
    p0 += __shfl_xor_sync(0xffffffffu, p0, 1);
    p0 += __shfl_xor_sync(0xffffffffu, p0, 2);
    p1 += __shfl_xor_sync(0xffffffffu, p1, 1);
    p1 += __shfl_xor_sync(0xffffffffu, p1, 2);
    if (qp == 0) {
        if (gm0 < RN) atomicAdd(&score[gm0], p0);
        if (gm1 < RN) atomicAdd(&score[gm1], p1);
    }
}

// ---------------- small compute kernels ----------------
__global__ void k_norm(const float* __restrict__ LR, const float* __restrict__ cs,
                       float* __restrict__ dX) {
    int i = blockIdx.x * blockDim.x + threadIdx.x;
    if (i < RN * DN) {
        int r = i >> 8, d = i & 255;
        dX[r * TWOD + d] = LR[i] / cs[r];
        dX[r * TWOD + DN + d] = LR[RN * DN + i] / cs[RN + r];
    }
}
__device__ __forceinline__ float warpSum(float v) {
#pragma unroll
    for (int o = 16; o; o >>= 1) v += __shfl_xor_sync(0xffffffffu, v, o);
    return v;
}
__device__ __forceinline__ float warpMax(float v) {
#pragma unroll
    for (int o = 16; o; o >>= 1) v = fmaxf(v, __shfl_xor_sync(0xffffffffu, v, o));
    return v;
}
// fused: per-block v1/v2 = w2@w1, w3@w1 into smem, then per-warp f1/f2 dots
__global__ __launch_bounds__(256) void k_f2(
    const float* __restrict__ w1, const float* __restrict__ w2, const float* __restrict__ w3,
    const float* __restrict__ b2, const float* __restrict__ b3,
    const float* __restrict__ feats, float* __restrict__ f1, float* __restrict__ f2) {
    __shared__ float v1s[TWOD], v2s[TWOD];
    int tid = threadIdx.x;
    for (int i = tid; i < TWOD; i += 256) {
        float s1 = 0.f, s2 = 0.f;
        for (int h = 0; h < HIDN; h++) {
            float w = w1[h * TWOD + i];
            s1 += w2[h] * w;
            s2 += w3[h] * w;
        }
        v1s[i] = s1;
        v2s[i] = s2;
    }
    __syncthreads();
    int gw = (blockIdx.x * 256 + tid) >> 5;
    int lane = tid & 31;
    if (gw >= RN) return;
    float s1 = 0.f, s2 = 0.f;
    for (int i = lane; i < TWOD; i += 32) {
        float x = feats[gw * TWOD + i];
        s1 += x * v1s[i];
        s2 += x * v2s[i];
    }
    s1 = warpSum(s1);
    s2 = warpSum(s2);
    if (lane == 0) { f1[gw] = s1 + b2[0]; f2[gw] = s2 + b3[0]; }
}
// softmax coef row; also seeds score[r] = b_sp (consumed+accumulated by gemm_small)
__global__ __launch_bounds__(512) void k_coef(const float* __restrict__ f1,
                                              const float* __restrict__ f2,
                                              const float* __restrict__ adj,
                                              __nv_bfloat16* __restrict__ coefbf,
                                              const float* __restrict__ bsp,
                                              float* __restrict__ score) {
    int r = blockIdx.x;
    int tid = threadIdx.x;
    __shared__ float red[512];
    if (tid == 0) score[r] = bsp[0];
    float f1r = f1[r];
    float l = -INFINITY;
    if (tid < RN) {
        float a = adj[r * RN + tid];
        float x = a * (f1r + f2[tid]);
        l = x > 0.f ? x : SLOPE * x;
        if (!(a > 0.f)) l -= 1e9f;
    }
    red[tid] = l;
    __syncthreads();
    for (int s = 256; s > 0; s >>= 1) {
        if (tid < s) red[tid] = fmaxf(red[tid], red[tid + s]);
        __syncthreads();
    }
    float mx = red[0];
    __syncthreads();
    float e = (tid < RN) ? __expf(l - mx) : 0.f;
    red[tid] = e;
    __syncthreads();
    for (int s = 256; s > 0; s >>= 1) {
        if (tid < s) red[tid] += red[tid + s];
        __syncthreads();
    }
    float inv = 1.f / red[0];
    coefbf[(size_t)r * 512 + tid] = __float2bfloat16(e * inv);
}
// sparse attention: warp/row, bf16 gather (2-edge unrolled); fp32 out optional
__global__ __launch_bounds__(256) void k_satt(
    const __nv_bfloat16* __restrict__ Xsrc, const float* __restrict__ Xres,
    const float* __restrict__ score, const int* __restrict__ rptr,
    const int* __restrict__ perm, const int* __restrict__ rel, const int* __restrict__ col,
    float alpha, float* __restrict__ out, __nv_bfloat16* __restrict__ outbf) {
    int e = (blockIdx.x * blockDim.x + threadIdx.x) >> 5;
    int lane = threadIdx.x & 31;
    if (e >= EN) return;
    int s = rptr[e], t = rptr[e + 1];
    float acc[8];
#pragma unroll
    for (int i = 0; i < 8; i++) acc[i] = 0.f;
    if (t > s) {
        float m = -1e30f;
        for (int j = s + lane; j < t; j += 32) {
            float sc = score[rel[perm[j]]];
            float l = sc > 0.f ? sc : SLOPE * sc;
            m = fmaxf(m, l);
        }
        m = warpMax(m);
        float ssum = 0.f;
        for (int j = s + lane; j < t; j += 32) {
            float sc = score[rel[perm[j]]];
            float l = sc > 0.f ? sc : SLOPE * sc;
            ssum += __expf(l - m);
        }
        ssum = warpSum(ssum);
        float inv = 1.f / ssum;
        int j = s;
        for (; j + 1 < t; j += 2) {
            int id0 = perm[j], id1 = perm[j + 1];
            float sc0 = score[rel[id0]], sc1 = score[rel[id1]];
            float l0 = sc0 > 0.f ? sc0 : SLOPE * sc0;
            float l1 = sc1 > 0.f ? sc1 : SLOPE * sc1;
            float cf0 = __expf(l0 - m) * inv;
            float cf1 = __expf(l1 - m) * inv;
            uint4 v0 = ((const uint4*)(Xsrc + (size_t)col[id0] * DN))[lane];
            uint4 v1 = ((const uint4*)(Xsrc + (size_t)col[id1] * DN))[lane];
            float2 p;
            p = __bfloat1622float2(*(const __nv_bfloat162*)&v0.x);
            acc[0] += cf0 * p.x; acc[1] += cf0 * p.y;
            p = __bfloat1622float2(*(const __nv_bfloat162*)&v0.y);
            acc[2] += cf0 * p.x; acc[3] += cf0 * p.y;
            p = __bfloat1622float2(*(const __nv_bfloat162*)&v0.z);
            acc[4] += cf0 * p.x; acc[5] += cf0 * p.y;
            p = __bfloat1622float2(*(const __nv_bfloat162*)&v0.w);
            acc[6] += cf0 * p.x; acc[7] += cf0 * p.y;
            p = __bfloat1622float2(*(const __nv_bfloat162*)&v1.x);
            acc[0] += cf1 * p.x; acc[1] += cf1 * p.y;
            p = __bfloat1622float2(*(const __nv_bfloat162*)&v1.y);
            acc[2] += cf1 * p.x; acc[3] += cf1 * p.y;
            p = __bfloat1622float2(*(const __nv_bfloat162*)&v1.z);
            acc[4] += cf1 * p.x; acc[5] += cf1 * p.y;
            p = __bfloat1622float2(*(const __nv_bfloat162*)&v1.w);
            acc[6] += cf1 * p.x; acc[7] += cf1 * p.y;
        }
        if (j < t) {
            int id = perm[j];
            float sc = score[rel[id]];
            float l = sc > 0.f ? sc : SLOPE * sc;
            float cf = __expf(l - m) * inv;
            uint4 v = ((const uint4*)(Xsrc + (size_t)col[id] * DN))[lane];
            float2 p;
            p = __bfloat1622float2(*(const __nv_bfloat162*)&v.x);
            acc[0] += cf * p.x; acc[1] += cf * p.y;
            p = __bfloat1622float2(*(const __nv_bfloat162*)&v.y);
            acc[2] += cf * p.x; acc[3] += cf * p.y;
            p = __bfloat1622float2(*(const __nv_bfloat162*)&v.z);
            acc[4] += cf * p.x; acc[5] += cf * p.y;
            p = __bfloat1622float2(*(const __nv_bfloat162*)&v.w);
            acc[6] += cf * p.x; acc[7] += cf * p.y;
        }
    }
    size_t base = (size_t)e * DN;
    const float4* rr = (const float4*)(Xres + base);
    float4 r0 = rr[lane * 2], r1 = rr[lane * 2 + 1];
    float o[8];
    o[0] = r0.x + alpha * fmaxf(acc[0], 0.f);
    o[1] = r0.y + alpha * fmaxf(acc[1], 0.f);
    o[2] = r0.z + alpha * fmaxf(acc[2], 0.f);
    o[3] = r0.w + alpha * fmaxf(acc[3], 0.f);
    o[4] = r1.x + alpha * fmaxf(acc[4], 0.f);
    o[5] = r1.y + alpha * fmaxf(acc[5], 0.f);
    o[6] = r1.z + alpha * fmaxf(acc[6], 0.f);
    o[7] = r1.w + alpha * fmaxf(acc[7], 0.f);
    if (out) {
        ((float4*)(out + base))[lane * 2] = make_float4(o[0], o[1], o[2], o[3]);
        ((float4*)(out + base))[lane * 2 + 1] = make_float4(o[4], o[5], o[6], o[7]);
    }
    __nv_bfloat162 b0 = __floats2bfloat162_rn(o[0], o[1]);
    __nv_bfloat162 b1 = __floats2bfloat162_rn(o[2], o[3]);
    __nv_bfloat162 b2 = __floats2bfloat162_rn(o[4], o[5]);
    __nv_bfloat162 b3 = __floats2bfloat162_rn(o[6], o[7]);
    uint4 ob;
    ob.x = *(unsigned*)&b0; ob.y = *(unsigned*)&b1;
    ob.z = *(unsigned*)&b2; ob.w = *(unsigned*)&b3;
    ((uint4*)(outbf + base))[lane] = ob;
}
// GCN: warp/row, bf16 gather (2-edge unrolled)
__global__ __launch_bounds__(256) void k_gcn(
    const __nv_bfloat16* __restrict__ X, const float* __restrict__ w,
    const int* __restrict__ rptr, const int* __restrict__ perm,
    const float* __restrict__ val, const int* __restrict__ col, float* __restrict__ out) {
    int e = (blockIdx.x * blockDim.x + threadIdx.x) >> 5;
    int lane = threadIdx.x & 31;
    if (e >= EN) return;
    int s = rptr[e], t = rptr[e + 1];
    float acc[8];
#pragma unroll
    for (int i = 0; i < 8; i++) acc[i] = 0.f;
    int j = s;
    for (; j + 1 < t; j += 2) {
        int id0 = perm[j], id1 = perm[j + 1];
        float v0s = val[id0], v1s = val[id1];
        uint4 u0 = ((const uint4*)(X + (size_t)col[id0] * DN))[lane];
        uint4 u1 = ((const uint4*)(X + (size_t)col[id1] * DN))[lane];
        float2 p;
        p = __bfloat1622float2(*(const __nv_bfloat162*)&u0.x);
        acc[0] += v0s * p.x; acc[1] += v0s * p.y;
        p = __bfloat1622float2(*(const __nv_bfloat162*)&u0.y);
        acc[2] += v0s * p.x; acc[3] += v0s * p.y;
        p = __bfloat1622float2(*(const __nv_bfloat162*)&u0.z);
        acc[4] += v0s * p.x; acc[5] += v0s * p.y;
        p = __bfloat1622float2(*(const __nv_bfloat162*)&u0.w);
        acc[6] += v0s * p.x; acc[7] += v0s * p.y;
        p = __bfloat1622float2(*(const __nv_bfloat162*)&u1.x);
        acc[0] += v1s * p.x; acc[1] += v1s * p.y;
        p = __bfloat1622float2(*(const __nv_bfloat162*)&u1.y);
        acc[2] += v1s * p.x; acc[3] += v1s * p.y;
        p = __bfloat1622float2(*(const __nv_bfloat162*)&u1.z);
        acc[4] += v1s * p.x; acc[5] += v1s * p.y;
        p = __bfloat1622float2(*(const __nv_bfloat162*)&u1.w);
        acc[6] += v1s * p.x; acc[7] += v1s * p.y;
    }
    if (j < t) {
        int id = perm[j];
        float v = val[id];
        uint4 u = ((const uint4*)(X + (size_t)col[id] * DN))[lane];
        float2 p;
        p = __bfloat1622float2(*(const __nv_bfloat162*)&u.x);
        acc[0] += v * p.x; acc[1] += v * p.y;
        p = __bfloat1622float2(*(const __nv_bfloat162*)&u.y);
        acc[2] += v * p.x; acc[3] += v * p.y;
        p = __bfloat1622float2(*(const __nv_bfloat162*)&u.z);
        acc[4] += v * p.x; acc[5] += v * p.y;
        p = __bfloat1622float2(*(const __nv_bfloat162*)&u.w);
        acc[6] += v * p.x; acc[7] += v * p.y;
    }
    size_t base = (size_t)e * DN;
    int d = lane * 8;
    float4 o0 = make_float4(fmaxf(acc[0] * w[d], 0.f), fmaxf(acc[1] * w[d + 1], 0.f),
                            fmaxf(acc[2] * w[d + 2], 0.f), fmaxf(acc[3] * w[d + 3], 0.f));
    float4 o1 = make_float4(fmaxf(acc[4] * w[d + 4], 0.f), fmaxf(acc[5] * w[d + 5], 0.f),
                            fmaxf(acc[6] * w[d + 6], 0.f), fmaxf(acc[7] * w[d + 7], 0.f));
    ((float4*)(out + base))[lane * 2] = o0;
    ((float4*)(out + base))[lane * 2 + 1] = o1;
}

// ---------------- host ----------------
extern "C" void kernel_launch(void* const* d_in, const int* in_sizes, int n_in,
                              void* d_out, int out_size) {
    const float* X0 = (const float*)d_in[0];
    const float* head_r = (const float*)d_in[1];
    const float* tail_r = (const float*)d_in[2];
    const float* dual_A = (const float*)d_in[3];
    const int* erow = (const int*)d_in[4];
    const int* ecol = (const int*)d_in[5];
    const int* erel = (const int*)d_in[6];
    const int* mrow = (const int*)d_in[7];
    const int* mcol = (const int*)d_in[8];
    const float* mval = (const float*)d_in[9];
    const float* w_self1 = (const float*)d_in[10];
    const float* w_self2 = (const float*)d_in[11];
    const float* b_self2 = (const float*)d_in[12];
    const float* w_self3 = (const float*)d_in[13];
    const float* b_self3 = (const float*)d_in[14];
    const float* w_sp1 = (const float*)d_in[15];
    const float* b_sp1 = (const float*)d_in[16];
    const float* w_dual1 = (const float*)d_in[17];
    const float* w_dual2 = (const float*)d_in[18];
    const float* b_dual2 = (const float*)d_in[19];
    const float* w_dual3 = (const float*)d_in[20];
    const float* b_dual3 = (const float*)d_in[21];
    const float* w_sp2 = (const float*)d_in[22];
    const float* b_sp2 = (const float*)d_in[23];
    const float* w_gcn1 = (const float*)d_in[24];
    const float* w_gcn2 = (const float*)d_in[25];
    const float* k_hw1 = (const float*)d_in[26];
    const float* bg_hw1 = (const float*)d_in[27];
    const float* k_hw2 = (const float*)d_in[28];
    const float* bg_hw2 = (const float*)d_in[29];
    float* outp = (float*)d_out;

    float *pX2, *gb, *h1, *LR, *cs, *dX, *dH1, *dH2, *f1, *f2, *score;
    __nv_bfloat16 *Xbf, *Xbf2, *Xbf3, *HT, *XT, *KwT1, *KwT2, *coefbf, *valsT;
    int *cntE, *cntM, *curE, *curM, *erptr, *eperm, *mrptr, *mperm;
    cudaGetSymbolAddress((void**)&pX2, g_pX2);
    cudaGetSymbolAddress((void**)&gb, g_gb);
    cudaGetSymbolAddress((void**)&h1, g_h1);
    cudaGetSymbolAddress((void**)&Xbf, g_Xbf);
    cudaGetSymbolAddress((void**)&Xbf2, g_Xbf2);
    cudaGetSymbolAddress((void**)&Xbf3, g_Xbf3);
    cudaGetSymbolAddress((void**)&HT, g_HT);
    cudaGetSymbolAddress((void**)&XT, g_XT);
    cudaGetSymbolAddress((void**)&KwT1, g_KwT1);
    cudaGetSymbolAddress((void**)&KwT2, g_KwT2);
    cudaGetSymbolAddress((void**)&coefbf, g_coefbf);
    cudaGetSymbolAddress((void**)&valsT, g_valsT);
    cudaGetSymbolAddress((void**)&LR, g_LR);
    cudaGetSymbolAddress((void**)&cs, g_cs);
    cudaGetSymbolAddress((void**)&dX, g_dX);
    cudaGetSymbolAddress((void**)&dH1, g_dH1);
    cudaGetSymbolAddress((void**)&dH2, g_dH2);
    cudaGetSymbolAddress((void**)&f1, g_f1);
    cudaGetSymbolAddress((void**)&f2, g_f2);
    cudaGetSymbolAddress((void**)&score, g_score);
    cudaGetSymbolAddress((void**)&cntE, g_cntE);
    cudaGetSymbolAddress((void**)&cntM, g_cntM);
    cudaGetSymbolAddress((void**)&curE, g_curE);
    cudaGetSymbolAddress((void**)&curM, g_curM);
    cudaGetSymbolAddress((void**)&erptr, g_erptr);
    cudaGetSymbolAddress((void**)&eperm, g_eperm);
    cudaGetSymbolAddress((void**)&mrptr, g_mrptr);
    cudaGetSymbolAddress((void**)&mperm, g_mperm);

    const int T = 256;
    int gRD = (RN * DN + T - 1) / T;
    int gNE = (NEDGE + T - 1) / T;
    int gFW = (RN * 32 + T - 1) / T;
    int gRow = (EN * 32 + T - 1) / T;
    dim3 gT(KP / 32, 16);
    dim3 gTX9(KP / 32, 9);
    dim3 gPX(KP / 32, 9);
    dim3 gg(8, 2, GEMM_Z);
    dim3 gGate((EN + 127) / 128, DN / 128);
    dim3 gSm((RN + BM - 1) / BM, TWOD / BN);
    dim3 gTr(16, 16);

    // setup; launch 4 = fused big GEMM (ncu capture slot)
    k_prepX_init<<<gPX, T>>>(X0, XT, Xbf, LR, cs, cntE, cntM, k_hw1, k_hw2, KwT1, KwT2);
    k_prepT<<<gT, T>>>(head_r, HT, cs, RN);
    k_prepT<<<gT, T>>>(tail_r, HT + (size_t)500 * KP, cs + 500, RN);
    k_gemm_tn<<<gg, T>>>(HT, XT, LR, 1000);
    k_norm<<<gRD, T>>>(LR, cs, dX);
    // CSR builds (fused)
    k_hist2<<<gNE, T>>>(erow, mrow, cntE, cntM);
    k_scan2<<<1, 1024>>>(cntE, erptr, curE, cntM, mrptr, curM);
    k_scatter2<<<gNE, T>>>(erow, curE, eperm, mrow, curM, mperm);
    // dense att 1 (v fused into f; score fused into gemm_small)
    k_f2<<<gFW, T>>>(w_self1, w_self2, w_self3, b_self2, b_self3, dX, f1, f2);
    k_coef<<<RN, 512>>>(f1, f2, dual_A, coefbf, b_sp1, score);
    k_transpT<<<gTr, T>>>(dX, valsT);
    k_gemm_small<<<gSm, T>>>(coefbf, valsT, dH1, w_sp1, score);
    // sparse att 1
    k_satt<<<gRow, T>>>(Xbf, X0, score, erptr, eperm, erel, ecol, 0.1f, (float*)0, Xbf2);
    // compute_r(pX1)
    k_transpTbf<<<gTX9, T>>>(Xbf2, XT, LR);
    k_gemm_tn<<<gg, T>>>(HT, XT, LR, 1000);
    k_norm<<<gRD, T>>>(LR, cs, dX);
    // dense att 2
    k_f2<<<gFW, T>>>(w_dual1, w_dual2, w_dual3, b_dual2, b_dual3, dX, f1, f2);
    k_coef<<<RN, 512>>>(f1, f2, dual_A, coefbf, b_sp2, score);
    k_transpT<<<gTr, T>>>(dH1, valsT);
    k_gemm_small<<<gSm, T>>>(coefbf, valsT, dH2, w_sp2, score);
    // sparse att 2
    k_satt<<<gRow, T>>>(Xbf2, X0, score, erptr, eperm, erel, ecol, 0.3f, pX2, Xbf3);
    // GCN + highway
    k_gcn<<<gRow, T>>>(Xbf3, w_gcn1, mrptr, mperm, mval, mcol, gb);
    k_gate128<<<gGate, T>>>(Xbf3, KwT1, bg_hw1, gb, pX2, h1, Xbf);
    k_gcn<<<gRow, T>>>(Xbf, w_gcn2, mrptr, mperm, mval, mcol, gb);
    k_gate128<<<gGate, T>>>(Xbf, KwT2, bg_hw2, gb, h1, outp, (__nv_bfloat16*)0);
}

// round 15
// speedup vs baseline: 1.4312x; 1.0051x over previous
#include <cuda_runtime.h>
#include <cuda_bf16.h>
#include <math.h>

#define EN 50000
#define RN 500
#define DN 256
#define NEDGE 500000
#define TWOD 512
#define HIDN 128
#define SLOPE 0.01f
#define KP 50048
#define TOTKB (KP / 32)
#define GEMM_Z 37
#define GEMM_KBPC 43
#define GSTR 40

// ---------------- static scratch ----------------
__device__ float g_pX2[EN * DN];
__device__ float g_gb[EN * DN];
__device__ float g_h1[EN * DN];
__device__ __nv_bfloat16 g_Xbf[EN * DN];
__device__ __nv_bfloat16 g_Xbf2[EN * DN];
__device__ __nv_bfloat16 g_Xbf3[EN * DN];
__device__ __nv_bfloat16 g_HT[1000 * KP];
__device__ __nv_bfloat16 g_XT[DN * KP];
__device__ __nv_bfloat16 g_KwT1[DN * DN];
__device__ __nv_bfloat16 g_KwT2[DN * DN];
__device__ __nv_bfloat16 g_coefbf[512 * 512];
__device__ __nv_bfloat16 g_valsT[512 * 512];
__device__ float g_LR[1000 * DN];
__device__ float g_cs[1000];
__device__ float g_dX[RN * TWOD];
__device__ float g_dH1[RN * TWOD];
__device__ float g_dH2[RN * TWOD];
__device__ float g_f1[RN];
__device__ float g_f2[RN];
__device__ float g_score[RN];
__device__ int g_cntE[EN];
__device__ int g_cntM[EN];
__device__ int g_curE[EN];
__device__ int g_curM[EN];
__device__ int g_erptr[EN + 1];
__device__ int g_mrptr[EN + 1];
__device__ int g_relp[NEDGE];   // rel[] permuted into CSR order (e-graph)
__device__ int g_colpE[NEDGE];  // ecol[] permuted (e-graph)
__device__ float g_valp[NEDGE]; // mval[] permuted (m-graph)
__device__ int g_colpM[NEDGE];  // mcol[] permuted (m-graph)

// ---------------- fused X-transpose + global init + Kw prep ----------------
__global__ void k_prepX_init(const float* __restrict__ In, __nv_bfloat16* __restrict__ OutT,
                             __nv_bfloat16* __restrict__ Rowbf, float* __restrict__ LR,
                             float* __restrict__ cs, int* cE, int* cM,
                             const float* __restrict__ K1, const float* __restrict__ K2,
                             __nv_bfloat16* __restrict__ T1, __nv_bfloat16* __restrict__ T2) {
    if (blockIdx.y == 8) {
        int i = blockIdx.x * blockDim.x + threadIdx.x;
        if (i < 1000 * DN) LR[i] = 0.f;
        if (i < 1000) cs[i] = 0.f;
        if (i < EN) { cE[i] = 0; cM[i] = 0; }
        if (i < DN * DN) {
            int n = i >> 8, k = i & 255;
            T1[i] = __float2bfloat16(K1[k * DN + n]);
            T2[i] = __float2bfloat16(K2[k * DN + n]);
        }
        return;
    }
    __shared__ float tile[32][33];
    int e0 = blockIdx.x * 32, r0 = blockIdx.y * 32;
    int tx = threadIdx.x & 31, ty = threadIdx.x >> 5;
#pragma unroll
    for (int j = 0; j < 4; j++) {
        int e = e0 + ty + j * 8, r = r0 + tx;
        float v = (e < EN) ? In[(size_t)e * DN + r] : 0.f;
        tile[ty + j * 8][tx] = v;
        if (e < EN) Rowbf[(size_t)e * DN + r] = __float2bfloat16(v);
    }
    __syncthreads();
#pragma unroll
    for (int j = 0; j < 4; j++) {
        int r = r0 + ty + j * 8, e = e0 + tx;
        OutT[(size_t)r * KP + e] = __float2bfloat16(tile[tx][ty + j * 8]);
    }
}

// fused head+tail transpose: y<16 -> head rows, y>=16 -> tail rows (+500 offset)
__global__ void k_prepHT(const float* __restrict__ Head, const float* __restrict__ Tail,
                         __nv_bfloat16* __restrict__ OutT, float* __restrict__ colsum) {
    __shared__ float tile[32][33];
    int isTail = blockIdx.y >= 16;
    const float* In = isTail ? Tail : Head;
    int r0 = (blockIdx.y - (isTail ? 16 : 0)) * 32;
    size_t obase = isTail ? (size_t)500 * KP : 0;
    int csoff = isTail ? 500 : 0;
    int e0 = blockIdx.x * 32;
    int tx = threadIdx.x & 31, ty = threadIdx.x >> 5;
#pragma unroll
    for (int j = 0; j < 4; j++) {
        int e = e0 + ty + j * 8, r = r0 + tx;
        tile[ty + j * 8][tx] = (e < EN && r < RN) ? In[(size_t)e * RN + r] : 0.f;
    }
    __syncthreads();
#pragma unroll
    for (int j = 0; j < 4; j++) {
        int r = r0 + ty + j * 8, e = e0 + tx;
        if (r < RN) OutT[obase + (size_t)r * KP + e] = __float2bfloat16(tile[tx][ty + j * 8]);
    }
    if (ty == 0 && r0 + tx < RN) {
        float s = 0.f;
#pragma unroll
        for (int e = 0; e < 32; e++) s += tile[e][tx];
        atomicAdd(&colsum[csoff + r0 + tx], s);
    }
}

// transpose bf16 [EN][DN] -> [DN][KP] bf16 (pad zero); extra y-slice zeros LR
__global__ void k_transpTbf(const __nv_bfloat16* __restrict__ In,
                            __nv_bfloat16* __restrict__ OutT, float* __restrict__ LR) {
    if (blockIdx.y == 8) {
        int i = blockIdx.x * blockDim.x + threadIdx.x;
        if (i < 1000 * DN) LR[i] = 0.f;
        return;
    }
    __shared__ __nv_bfloat16 tile[32][33];
    int e0 = blockIdx.x * 32, r0 = blockIdx.y * 32;
    int tx = threadIdx.x & 31, ty = threadIdx.x >> 5;
#pragma unroll
    for (int j = 0; j < 4; j++) {
        int e = e0 + ty + j * 8, r = r0 + tx;
        tile[ty + j * 8][tx] = (e < EN) ? In[(size_t)e * DN + r] : __float2bfloat16(0.f);
    }
    __syncthreads();
#pragma unroll
    for (int j = 0; j < 4; j++) {
        int r = r0 + ty + j * 8, e = e0 + tx;
        OutT[(size_t)r * KP + e] = tile[tx][ty + j * 8];
    }
}

// vals [RN][512] fp32 -> valsT [512][512] bf16
__global__ void k_transpT(const float* __restrict__ in, __nv_bfloat16* __restrict__ out) {
    __shared__ float tile[32][33];
    int j0 = blockIdx.x * 32, d0 = blockIdx.y * 32;
    int tx = threadIdx.x & 31, ty = threadIdx.x >> 5;
#pragma unroll
    for (int jj = 0; jj < 4; jj++) {
        int j = j0 + ty + jj * 8;
        tile[ty + jj * 8][tx] = (j < RN) ? in[(size_t)j * TWOD + d0 + tx] : 0.f;
    }
    __syncthreads();
#pragma unroll
    for (int jj = 0; jj < 4; jj++) {
        int d = d0 + ty + jj * 8;
        out[(size_t)d * 512 + j0 + tx] = __float2bfloat16(tile[tx][ty + jj * 8]);
    }
}

// ---------------- CSR build (both graphs fused; payloads permuted inline) -------------
__global__ void k_hist2(const int* __restrict__ er, const int* __restrict__ mr, int* cE,
                        int* cM) {
    int i = blockIdx.x * blockDim.x + threadIdx.x;
    if (i < NEDGE) {
        atomicAdd(&cE[er[i]], 1);
        atomicAdd(&cM[mr[i]], 1);
    }
}
__global__ void k_scan2(const int* __restrict__ cA, int* __restrict__ pA, int* __restrict__ uA,
                        const int* __restrict__ cB, int* __restrict__ pB, int* __restrict__ uB) {
    __shared__ int wsum[32];
    __shared__ int s_run;
    int tid = threadIdx.x, lane = tid & 31, w = tid >> 5;
    for (int g = 0; g < 2; g++) {
        const int* cnt = g ? cB : cA;
        int* ptr = g ? pB : pA;
        int* cur = g ? uB : uA;
        if (tid == 0) s_run = 0;
        __syncthreads();
        for (int base = 0; base < EN; base += 1024) {
            int i = base + tid;
            int v = (i < EN) ? cnt[i] : 0;
            int x = v;
#pragma unroll
            for (int o = 1; o < 32; o <<= 1) {
                int y = __shfl_up_sync(0xffffffffu, x, o);
                if (lane >= o) x += y;
            }
            if (lane == 31) wsum[w] = x;
            __syncthreads();
            if (w == 0) {
                int s = wsum[lane];
#pragma unroll
                for (int o = 1; o < 32; o <<= 1) {
                    int y = __shfl_up_sync(0xffffffffu, s, o);
                    if (lane >= o) s += y;
                }
                wsum[lane] = s;
            }
            __syncthreads();
            int excl = s_run + x - v + (w ? wsum[w - 1] : 0);
            if (i < EN) { ptr[i] = excl; cur[i] = excl; }
            __syncthreads();
            if (tid == 1023) s_run += wsum[31];
            __syncthreads();
        }
        if (tid == 0) ptr[EN] = s_run;
        __syncthreads();
    }
}
__global__ void k_scatter2(const int* __restrict__ er, int* uE, const int* __restrict__ rel,
                           const int* __restrict__ ecol, int* __restrict__ relp,
                           int* __restrict__ colpE, const int* __restrict__ mr, int* uM,
                           const float* __restrict__ mval, const int* __restrict__ mcol,
                           float* __restrict__ valp, int* __restrict__ colpM) {
    int i = blockIdx.x * blockDim.x + threadIdx.x;
    if (i < NEDGE) {
        int pe_ = atomicAdd(&uE[er[i]], 1);
        relp[pe_] = rel[i];
        colpE[pe_] = ecol[i];
        int pm_ = atomicAdd(&uM[mr[i]], 1);
        valp[pm_] = mval[i];
        colpM[pm_] = mcol[i];
    }
}

// ---------------- mma helpers ----------------
__device__ __forceinline__ void mma16816(float* c, unsigned a0, unsigned a1, unsigned a2,
                                         unsigned a3, unsigned b0, unsigned b1) {
    asm volatile(
        "mma.sync.aligned.m16n8k16.row.col.f32.bf16.bf16.f32 "
        "{%0,%1,%2,%3},{%4,%5,%6,%7},{%8,%9},{%0,%1,%2,%3};\n"
        : "+f"(c[0]), "+f"(c[1]), "+f"(c[2]), "+f"(c[3])
        : "r"(a0), "r"(a1), "r"(a2), "r"(a3), "r"(b0), "r"(b1));
}
__device__ __forceinline__ void cpa16(unsigned s, const void* g) {
    asm volatile("cp.async.cg.shared.global [%0], [%1], 16;\n" ::"r"(s), "l"(g));
}
__device__ __forceinline__ void ldsm4(unsigned* r, unsigned addr) {
    asm volatile("ldmatrix.sync.aligned.m8n8.x4.shared.b16 {%0,%1,%2,%3}, [%4];\n"
                 : "=r"(r[0]), "=r"(r[1]), "=r"(r[2]), "=r"(r[3])
                 : "r"(addr));
}

// ---------------- fused big TN GEMM (BK=32, 2-stage, static smem, ldmatrix) -----------
__global__ __launch_bounds__(256) void k_gemm_tn(
    const __nv_bfloat16* __restrict__ A, const __nv_bfloat16* __restrict__ B,
    float* __restrict__ C, int M) {
    __shared__ __nv_bfloat16 As[2][128 * GSTR];
    __shared__ __nv_bfloat16 Bs[2][128 * GSTR];
    int t = threadIdx.x;
    int mbase = blockIdx.x * 128, nbase = blockIdx.y * 128;
    int kb0 = blockIdx.z * GEMM_KBPC;
    int kb1 = min(TOTKB, kb0 + GEMM_KBPC);
    if (kb0 >= kb1) return;
    int niter = kb1 - kb0;
    unsigned sA = (unsigned)__cvta_generic_to_shared(&As[0][0]);
    unsigned sB = (unsigned)__cvta_generic_to_shared(&Bs[0][0]);
    int row_ = t >> 2, ch = t & 3;
    const __nv_bfloat16* gA0 = A + (size_t)min(mbase + row_, M - 1) * KP + ch * 8;
    const __nv_bfloat16* gA1 = A + (size_t)min(mbase + 64 + row_, M - 1) * KP + ch * 8;
    const __nv_bfloat16* gB0 = B + (size_t)(nbase + row_) * KP + ch * 8;
    const __nv_bfloat16* gB1 = B + (size_t)(nbase + 64 + row_) * KP + ch * 8;
    unsigned oA0 = sA + (row_ * GSTR + ch * 8) * 2, oA1 = oA0 + 64 * GSTR * 2;
    unsigned oB0 = sB + (row_ * GSTR + ch * 8) * 2, oB1 = oB0 + 64 * GSTR * 2;
    const unsigned BUFB = 128 * GSTR * 2;
    {
        long k0 = (long)kb0 * 32;
        cpa16(oA0, gA0 + k0); cpa16(oA1, gA1 + k0);
        cpa16(oB0, gB0 + k0); cpa16(oB1, gB1 + k0);
        asm volatile("cp.async.commit_group;\n");
    }
    float c[2][8][4];
#pragma unroll
    for (int mt = 0; mt < 2; mt++)
#pragma unroll
        for (int f = 0; f < 8; f++)
#pragma unroll
            for (int i = 0; i < 4; i++) c[mt][f][i] = 0.f;
    int w = t >> 5, lane = t & 31;
    int wm = (w & 3) * 32, wn = (w >> 2) * 64;
    unsigned aoff = sA + ((wm + (lane & 15)) * GSTR + (lane >> 4) * 8) * 2;
    unsigned boff = sB + ((wn + (lane & 7) + ((lane >> 4) << 3)) * GSTR + ((lane >> 3) & 1) * 8) * 2;
    for (int i = 0; i < niter; i++) {
        int cur = i & 1, nxt = cur ^ 1;
        if (i + 1 < niter) {
            long k = (long)(kb0 + i + 1) * 32;
            cpa16(oA0 + nxt * BUFB, gA0 + k); cpa16(oA1 + nxt * BUFB, gA1 + k);
            cpa16(oB0 + nxt * BUFB, gB0 + k); cpa16(oB1 + nxt * BUFB, gB1 + k);
        }
        asm volatile("cp.async.commit_group;\n");
        asm volatile("cp.async.wait_group 1;\n");
        __syncthreads();
        unsigned aC = aoff + cur * BUFB, bC = boff + cur * BUFB;
#pragma unroll
        for (int kk = 0; kk < 32; kk += 16) {
            unsigned A0[4], A1[4];
            ldsm4(A0, aC + kk * 2);
            ldsm4(A1, aC + (16 * GSTR + kk) * 2);
#pragma unroll
            for (int p = 0; p < 4; p++) {
                unsigned B4[4];
                ldsm4(B4, bC + (p * 16 * GSTR + kk) * 2);
                mma16816(c[0][2 * p], A0[0], A0[1], A0[2], A0[3], B4[0], B4[1]);
                mma16816(c[1][2 * p], A1[0], A1[1], A1[2], A1[3], B4[0], B4[1]);
                mma16816(c[0][2 * p + 1], A0[0], A0[1], A0[2], A0[3], B4[2], B4[3]);
                mma16816(c[1][2 * p + 1], A1[0], A1[1], A1[2], A1[3], B4[2], B4[3]);
            }
        }
        __syncthreads();
    }
    int gi = lane >> 2, qp = lane & 3;
#pragma unroll
    for (int mt = 0; mt < 2; mt++)
#pragma unroll
        for (int f = 0; f < 8; f++) {
            int gm0 = mbase + wm + mt * 16 + gi, gm1 = gm0 + 8;
            int gn = nbase + wn + f * 8 + qp * 2;
            if (gm0 < M) {
                atomicAdd(&C[gm0 * DN + gn], c[mt][f][0]);
                atomicAdd(&C[gm0 * DN + gn + 1], c[mt][f][1]);
            }
            if (gm1 < M) {
                atomicAdd(&C[gm1 * DN + gn], c[mt][f][2]);
                atomicAdd(&C[gm1 * DN + gn + 1], c[mt][f][3]);
            }
        }
}

// ---------------- gate GEMM (BK=32, K=256, static smem, highway fused, ldmatrix) ------
__global__ __launch_bounds__(256) void k_gate128(
    const __nv_bfloat16* __restrict__ Abf, const __nv_bfloat16* __restrict__ KwT,
    const float* __restrict__ bg, const float* __restrict__ G, const float* __restrict__ L1,
    float* __restrict__ H, __nv_bfloat16* __restrict__ Hbf) {
    __shared__ __nv_bfloat16 As[2][128 * GSTR];
    __shared__ __nv_bfloat16 Bs[2][128 * GSTR];
    int t = threadIdx.x;
    int mbase = blockIdx.x * 128, nbase = blockIdx.y * 128;
    unsigned sA = (unsigned)__cvta_generic_to_shared(&As[0][0]);
    unsigned sB = (unsigned)__cvta_generic_to_shared(&Bs[0][0]);
    int row_ = t >> 2, ch = t & 3;
    const __nv_bfloat16* gA0 = Abf + (size_t)min(mbase + row_, EN - 1) * DN + ch * 8;
    const __nv_bfloat16* gA1 = Abf + (size_t)min(mbase + 64 + row_, EN - 1) * DN + ch * 8;
    const __nv_bfloat16* gB0 = KwT + (size_t)(nbase + row_) * DN + ch * 8;
    const __nv_bfloat16* gB1 = KwT + (size_t)(nbase + 64 + row_) * DN + ch * 8;
    unsigned oA0 = sA + (row_ * GSTR + ch * 8) * 2, oA1 = oA0 + 64 * GSTR * 2;
    unsigned oB0 = sB + (row_ * GSTR + ch * 8) * 2, oB1 = oB0 + 64 * GSTR * 2;
    const unsigned BUFB = 128 * GSTR * 2;
    cpa16(oA0, gA0); cpa16(oA1, gA1);
    cpa16(oB0, gB0); cpa16(oB1, gB1);
    asm volatile("cp.async.commit_group;\n");
    float c[2][8][4];
#pragma unroll
    for (int mt = 0; mt < 2; mt++)
#pragma unroll
        for (int f = 0; f < 8; f++)
#pragma unroll
            for (int i = 0; i < 4; i++) c[mt][f][i] = 0.f;
    int w = t >> 5, lane = t & 31;
    int wm = (w & 3) * 32, wn = (w >> 2) * 64;
    unsigned aoff = sA + ((wm + (lane & 15)) * GSTR + (lane >> 4) * 8) * 2;
    unsigned boff = sB + ((wn + (lane & 7) + ((lane >> 4) << 3)) * GSTR + ((lane >> 3) & 1) * 8) * 2;
    const int NIT = DN / 32;
#pragma unroll
    for (int i = 0; i < NIT; i++) {
        int cur = i & 1, nxt = cur ^ 1;
        if (i + 1 < NIT) {
            int k = (i + 1) * 32;
            cpa16(oA0 + nxt * BUFB, gA0 + k); cpa16(oA1 + nxt * BUFB, gA1 + k);
            cpa16(oB0 + nxt * BUFB, gB0 + k); cpa16(oB1 + nxt * BUFB, gB1 + k);
        }
        asm volatile("cp.async.commit_group;\n");
        asm volatile("cp.async.wait_group 1;\n");
        __syncthreads();
        unsigned aC = aoff + cur * BUFB, bC = boff + cur * BUFB;
#pragma unroll
        for (int kk = 0; kk < 32; kk += 16) {
            unsigned A0[4], A1[4];
            ldsm4(A0, aC + kk * 2);
            ldsm4(A1, aC + (16 * GSTR + kk) * 2);
#pragma unroll
            for (int p = 0; p < 4; p++) {
                unsigned B4[4];
                ldsm4(B4, bC + (p * 16 * GSTR + kk) * 2);
                mma16816(c[0][2 * p], A0[0], A0[1], A0[2], A0[3], B4[0], B4[1]);
                mma16816(c[1][2 * p], A1[0], A1[1], A1[2], A1[3], B4[0], B4[1]);
                mma16816(c[0][2 * p + 1], A0[0], A0[1], A0[2], A0[3], B4[2], B4[3]);
                mma16816(c[1][2 * p + 1], A1[0], A1[1], A1[2], A1[3], B4[2], B4[3]);
            }
        }
        __syncthreads();
    }
    int gi = lane >> 2, qp = lane & 3;
#pragma unroll
    for (int mt = 0; mt < 2; mt++)
#pragma unroll
        for (int f = 0; f < 8; f++) {
            int gn = nbase + wn + f * 8 + qp * 2;
#pragma unroll
            for (int half = 0; half < 2; half++) {
                int gm = mbase + wm + mt * 16 + gi + half * 8;
                if (gm < EN) {
#pragma unroll
                    for (int j = 0; j < 2; j++) {
                        float z = c[mt][f][half * 2 + j] + bg[gn + j];
                        float tg = 1.f / (1.f + __expf(-z));
                        size_t off = (size_t)gm * DN + gn + j;
                        float hv = tg * G[off] + (1.f - tg) * L1[off];
                        H[off] = hv;
                        if (Hbf) Hbf[off] = __float2bfloat16(hv);
                    }
                }
            }
        }
}

// ------- small dense-att GEMM: dH = relu(coef @ valsT^T), K=512, + fused score -------
#define BM 64
#define BN 64
#define BKK 32
#define ASTR 40
__global__ __launch_bounds__(256) void k_gemm_small(const __nv_bfloat16* __restrict__ A,
                                                    const __nv_bfloat16* __restrict__ B,
                                                    float* __restrict__ C,
                                                    const float* __restrict__ wsp,
                                                    float* __restrict__ score) {
    __shared__ __nv_bfloat16 Asm[BM * ASTR];
    __shared__ __nv_bfloat16 Bsm[BN * ASTR];
    int t = threadIdx.x;
    int mbase = blockIdx.x * BM, nbase = blockIdx.y * BN;
    int w = t >> 5, lane = t & 31;
    int wm = (w & 3) * 16, wn = (w >> 2) * 32;
    int row = lane >> 2, qp = lane & 3;
    float c[4][4];
#pragma unroll
    for (int f = 0; f < 4; f++)
#pragma unroll
        for (int i = 0; i < 4; i++) c[f][i] = 0.f;
    for (int kb = 0; kb < 512; kb += BKK) {
#pragma unroll
        for (int i = 0; i < 8; i++) {
            int idx = t + i * 256;
            int m = idx >> 5, k = idx & 31;
            int gm = min(mbase + m, RN - 1);
            Asm[m * ASTR + k] = A[(size_t)gm * 512 + kb + k];
        }
#pragma unroll
        for (int i = 0; i < 8; i++) {
            int idx = t + i * 256;
            int n = idx >> 5, k = idx & 31;
            Bsm[n * ASTR + k] = B[(size_t)(nbase + n) * 512 + kb + k];
        }
        __syncthreads();
#pragma unroll
        for (int kk = 0; kk < BKK; kk += 16) {
            unsigned a0 = *(const unsigned*)&Asm[(wm + row) * ASTR + kk + qp * 2];
            unsigned a1 = *(const unsigned*)&Asm[(wm + row + 8) * ASTR + kk + qp * 2];
            unsigned a2 = *(const unsigned*)&Asm[(wm + row) * ASTR + kk + 8 + qp * 2];
            unsigned a3 = *(const unsigned*)&Asm[(wm + row + 8) * ASTR + kk + 8 + qp * 2];
#pragma unroll
            for (int f = 0; f < 4; f++) {
                unsigned b0 = *(const unsigned*)&Bsm[(wn + f * 8 + row) * ASTR + kk + qp * 2];
                unsigned b1 = *(const unsigned*)&Bsm[(wn + f * 8 + row) * ASTR + kk + 8 + qp * 2];
                mma16816(c[f], a0, a1, a2, a3, b0, b1);
            }
        }
        __syncthreads();
    }
    float p0 = 0.f, p1 = 0.f;
    int gm0 = mbase + wm + row, gm1 = gm0 + 8;
#pragma unroll
    for (int f = 0; f < 4; f++) {
        int gn = nbase + wn + f * 8 + qp * 2;
        float w0 = wsp[gn], w1v = wsp[gn + 1];
        float r00 = fmaxf(c[f][0], 0.f), r01 = fmaxf(c[f][1], 0.f);
        float r10 = fmaxf(c[f][2], 0.f), r11 = fmaxf(c[f][3], 0.f);
        if (gm0 < RN) {
            C[(size_t)gm0 * TWOD + gn] = r00;
            C[(size_t)gm0 * TWOD + gn + 1] = r01;
        }
        if (gm1 < RN) {
            C[(size_t)gm1 * TWOD + gn] = r10;
            C[(size_t)gm1 * TWOD + gn + 1] = r11;
        }
        p0 += r00 * w0 + r01 * w1v;
        p1 += r10 * w0 + r11 * w1v;
    }
    p0 += __shfl_xor_sync(0xffffffffu, p0, 1);
    p0 += __shfl_xor_sync(0xffffffffu, p0, 2);
    p1 += __shfl_xor_sync(0xffffffffu, p1, 1);
    p1 += __shfl_xor_sync(0xffffffffu, p1, 2);
    if (qp == 0) {
        if (gm0 < RN) atomicAdd(&score[gm0], p0);
        if (gm1 < RN) atomicAdd(&score[gm1], p1);
    }
}

// ---------------- small compute kernels ----------------
__global__ void k_norm(const float* __restrict__ LR, const float* __restrict__ cs,
                       float* __restrict__ dX) {
    int i = blockIdx.x * blockDim.x + threadIdx.x;
    if (i < RN * DN) {
        int r = i >> 8, d = i & 255;
        dX[r * TWOD + d] = LR[i] / cs[r];
        dX[r * TWOD + DN + d] = LR[RN * DN + i] / cs[RN + r];
    }
}
__device__ __forceinline__ float warpSum(float v) {
#pragma unroll
    for (int o = 16; o; o >>= 1) v += __shfl_xor_sync(0xffffffffu, v, o);
    return v;
}
__device__ __forceinline__ float warpMax(float v) {
#pragma unroll
    for (int o = 16; o; o >>= 1) v = fmaxf(v, __shfl_xor_sync(0xffffffffu, v, o));
    return v;
}
__global__ __launch_bounds__(256) void k_f2(
    const float* __restrict__ w1, const float* __restrict__ w2, const float* __restrict__ w3,
    const float* __restrict__ b2, const float* __restrict__ b3,
    const float* __restrict__ feats, float* __restrict__ f1, float* __restrict__ f2) {
    __shared__ float v1s[TWOD], v2s[TWOD];
    int tid = threadIdx.x;
    for (int i = tid; i < TWOD; i += 256) {
        float s1 = 0.f, s2 = 0.f;
        for (int h = 0; h < HIDN; h++) {
            float w = w1[h * TWOD + i];
            s1 += w2[h] * w;
            s2 += w3[h] * w;
        }
        v1s[i] = s1;
        v2s[i] = s2;
    }
    __syncthreads();
    int gw = (blockIdx.x * 256 + tid) >> 5;
    int lane = tid & 31;
    if (gw >= RN) return;
    float s1 = 0.f, s2 = 0.f;
    for (int i = lane; i < TWOD; i += 32) {
        float x = feats[gw * TWOD + i];
        s1 += x * v1s[i];
        s2 += x * v2s[i];
    }
    s1 = warpSum(s1);
    s2 = warpSum(s2);
    if (lane == 0) { f1[gw] = s1 + b2[0]; f2[gw] = s2 + b3[0]; }
}
__global__ __launch_bounds__(512) void k_coef(const float* __restrict__ f1,
                                              const float* __restrict__ f2,
                                              const float* __restrict__ adj,
                                              __nv_bfloat16* __restrict__ coefbf,
                                              const float* __restrict__ bsp,
                                              float* __restrict__ score) {
    int r = blockIdx.x;
    int tid = threadIdx.x;
    __shared__ float red[512];
    if (tid == 0) score[r] = bsp[0];
    float f1r = f1[r];
    float l = -INFINITY;
    if (tid < RN) {
        float a = adj[r * RN + tid];
        float x = a * (f1r + f2[tid]);
        l = x > 0.f ? x : SLOPE * x;
        if (!(a > 0.f)) l -= 1e9f;
    }
    red[tid] = l;
    __syncthreads();
    for (int s = 256; s > 0; s >>= 1) {
        if (tid < s) red[tid] = fmaxf(red[tid], red[tid + s]);
        __syncthreads();
    }
    float mx = red[0];
    __syncthreads();
    float e = (tid < RN) ? __expf(l - mx) : 0.f;
    red[tid] = e;
    __syncthreads();
    for (int s = 256; s > 0; s >>= 1) {
        if (tid < s) red[tid] += red[tid + s];
        __syncthreads();
    }
    float inv = 1.f / red[0];
    coefbf[(size_t)r * 512 + tid] = __float2bfloat16(e * inv);
}
// sparse attention: warp/row, smem leaky-score LUT, permuted payloads, bf16 gather
__global__ __launch_bounds__(256) void k_satt(
    const __nv_bfloat16* __restrict__ Xsrc, const float* __restrict__ Xres,
    const float* __restrict__ score, const int* __restrict__ rptr,
    const int* __restrict__ relp, const int* __restrict__ colp,
    float alpha, float* __restrict__ out, __nv_bfloat16* __restrict__ outbf) {
    __shared__ float lsc[RN];
    int tid = threadIdx.x;
    for (int i = tid; i < RN; i += 256) {
        float sc = score[i];
        lsc[i] = sc > 0.f ? sc : SLOPE * sc;
    }
    __syncthreads();
    int e = (blockIdx.x * blockDim.x + tid) >> 5;
    int lane = tid & 31;
    if (e >= EN) return;
    int s = rptr[e], t = rptr[e + 1];
    float acc[8];
#pragma unroll
    for (int i = 0; i < 8; i++) acc[i] = 0.f;
    if (t > s) {
        float m = -1e30f;
        for (int j = s + lane; j < t; j += 32) m = fmaxf(m, lsc[relp[j]]);
        m = warpMax(m);
        float ssum = 0.f;
        for (int j = s + lane; j < t; j += 32) ssum += __expf(lsc[relp[j]] - m);
        ssum = warpSum(ssum);
        float inv = 1.f / ssum;
        int j = s;
        for (; j + 1 < t; j += 2) {
            float cf0 = __expf(lsc[relp[j]] - m) * inv;
            float cf1 = __expf(lsc[relp[j + 1]] - m) * inv;
            uint4 v0 = ((const uint4*)(Xsrc + (size_t)colp[j] * DN))[lane];
            uint4 v1 = ((const uint4*)(Xsrc + (size_t)colp[j + 1] * DN))[lane];
            float2 p;
            p = __bfloat1622float2(*(const __nv_bfloat162*)&v0.x);
            acc[0] += cf0 * p.x; acc[1] += cf0 * p.y;
            p = __bfloat1622float2(*(const __nv_bfloat162*)&v0.y);
            acc[2] += cf0 * p.x; acc[3] += cf0 * p.y;
            p = __bfloat1622float2(*(const __nv_bfloat162*)&v0.z);
            acc[4] += cf0 * p.x; acc[5] += cf0 * p.y;
            p = __bfloat1622float2(*(const __nv_bfloat162*)&v0.w);
            acc[6] += cf0 * p.x; acc[7] += cf0 * p.y;
            p = __bfloat1622float2(*(const __nv_bfloat162*)&v1.x);
            acc[0] += cf1 * p.x; acc[1] += cf1 * p.y;
            p = __bfloat1622float2(*(const __nv_bfloat162*)&v1.y);
            acc[2] += cf1 * p.x; acc[3] += cf1 * p.y;
            p = __bfloat1622float2(*(const __nv_bfloat162*)&v1.z);
            acc[4] += cf1 * p.x; acc[5] += cf1 * p.y;
            p = __bfloat1622float2(*(const __nv_bfloat162*)&v1.w);
            acc[6] += cf1 * p.x; acc[7] += cf1 * p.y;
        }
        if (j < t) {
            float cf = __expf(lsc[relp[j]] - m) * inv;
            uint4 v = ((const uint4*)(Xsrc + (size_t)colp[j] * DN))[lane];
            float2 p;
            p = __bfloat1622float2(*(const __nv_bfloat162*)&v.x);
            acc[0] += cf * p.x; acc[1] += cf * p.y;
            p = __bfloat1622float2(*(const __nv_bfloat162*)&v.y);
            acc[2] += cf * p.x; acc[3] += cf * p.y;
            p = __bfloat1622float2(*(const __nv_bfloat162*)&v.z);
            acc[4] += cf * p.x; acc[5] += cf * p.y;
            p = __bfloat1622float2(*(const __nv_bfloat162*)&v.w);
            acc[6] += cf * p.x; acc[7] += cf * p.y;
        }
    }
    size_t base = (size_t)e * DN;
    const float4* rr = (const float4*)(Xres + base);
    float4 r0 = rr[lane * 2], r1 = rr[lane * 2 + 1];
    float o[8];
    o[0] = r0.x + alpha * fmaxf(acc[0], 0.f);
    o[1] = r0.y + alpha * fmaxf(acc[1], 0.f);
    o[2] = r0.z + alpha * fmaxf(acc[2], 0.f);
    o[3] = r0.w + alpha * fmaxf(acc[3], 0.f);
    o[4] = r1.x + alpha * fmaxf(acc[4], 0.f);
    o[5] = r1.y + alpha * fmaxf(acc[5], 0.f);
    o[6] = r1.z + alpha * fmaxf(acc[6], 0.f);
    o[7] = r1.w + alpha * fmaxf(acc[7], 0.f);
    if (out) {
        ((float4*)(out + base))[lane * 2] = make_float4(o[0], o[1], o[2], o[3]);
        ((float4*)(out + base))[lane * 2 + 1] = make_float4(o[4], o[5], o[6], o[7]);
    }
    __nv_bfloat162 b0 = __floats2bfloat162_rn(o[0], o[1]);
    __nv_bfloat162 b1 = __floats2bfloat162_rn(o[2], o[3]);
    __nv_bfloat162 b2 = __floats2bfloat162_rn(o[4], o[5]);
    __nv_bfloat162 b3 = __floats2bfloat162_rn(o[6], o[7]);
    uint4 ob;
    ob.x = *(unsigned*)&b0; ob.y = *(unsigned*)&b1;
    ob.z = *(unsigned*)&b2; ob.w = *(unsigned*)&b3;
    ((uint4*)(outbf + base))[lane] = ob;
}
// GCN: warp/row, permuted payloads, bf16 gather (2-edge unrolled)
__global__ __launch_bounds__(256) void k_gcn(
    const __nv_bfloat16* __restrict__ X, const float* __restrict__ w,
    const int* __restrict__ rptr, const float* __restrict__ valp,
    const int* __restrict__ colp, float* __restrict__ out) {
    int e = (blockIdx.x * blockDim.x + threadIdx.x) >> 5;
    int lane = threadIdx.x & 31;
    if (e >= EN) return;
    int s = rptr[e], t = rptr[e + 1];
    float acc[8];
#pragma unroll
    for (int i = 0; i < 8; i++) acc[i] = 0.f;
    int j = s;
    for (; j + 1 < t; j += 2) {
        float v0s = valp[j], v1s = valp[j + 1];
        uint4 u0 = ((const uint4*)(X + (size_t)colp[j] * DN))[lane];
        uint4 u1 = ((const uint4*)(X + (size_t)colp[j + 1] * DN))[lane];
        float2 p;
        p = __bfloat1622float2(*(const __nv_bfloat162*)&u0.x);
        acc[0] += v0s * p.x; acc[1] += v0s * p.y;
        p = __bfloat1622float2(*(const __nv_bfloat162*)&u0.y);
        acc[2] += v0s * p.x; acc[3] += v0s * p.y;
        p = __bfloat1622float2(*(const __nv_bfloat162*)&u0.z);
        acc[4] += v0s * p.x; acc[5] += v0s * p.y;
        p = __bfloat1622float2(*(const __nv_bfloat162*)&u0.w);
        acc[6] += v0s * p.x; acc[7] += v0s * p.y;
        p = __bfloat1622float2(*(const __nv_bfloat162*)&u1.x);
        acc[0] += v1s * p.x; acc[1] += v1s * p.y;
        p = __bfloat1622float2(*(const __nv_bfloat162*)&u1.y);
        acc[2] += v1s * p.x; acc[3] += v1s * p.y;
        p = __bfloat1622float2(*(const __nv_bfloat162*)&u1.z);
        acc[4] += v1s * p.x; acc[5] += v1s * p.y;
        p = __bfloat1622float2(*(const __nv_bfloat162*)&u1.w);
        acc[6] += v1s * p.x; acc[7] += v1s * p.y;
    }
    if (j < t) {
        float v = valp[j];
        uint4 u = ((const uint4*)(X + (size_t)colp[j] * DN))[lane];
        float2 p;
        p = __bfloat1622float2(*(const __nv_bfloat162*)&u.x);
        acc[0] += v * p.x; acc[1] += v * p.y;
        p = __bfloat1622float2(*(const __nv_bfloat162*)&u.y);
        acc[2] += v * p.x; acc[3] += v * p.y;
        p = __bfloat1622float2(*(const __nv_bfloat162*)&u.z);
        acc[4] += v * p.x; acc[5] += v * p.y;
        p = __bfloat1622float2(*(const __nv_bfloat162*)&u.w);
        acc[6] += v * p.x; acc[7] += v * p.y;
    }
    size_t base = (size_t)e * DN;
    int d = lane * 8;
    float4 o0 = make_float4(fmaxf(acc[0] * w[d], 0.f), fmaxf(acc[1] * w[d + 1], 0.f),
                            fmaxf(acc[2] * w[d + 2], 0.f), fmaxf(acc[3] * w[d + 3], 0.f));
    float4 o1 = make_float4(fmaxf(acc[4] * w[d + 4], 0.f), fmaxf(acc[5] * w[d + 5], 0.f),
                            fmaxf(acc[6] * w[d + 6], 0.f), fmaxf(acc[7] * w[d + 7], 0.f));
    ((float4*)(out + base))[lane * 2] = o0;
    ((float4*)(out + base))[lane * 2 + 1] = o1;
}

// ---------------- host ----------------
extern "C" void kernel_launch(void* const* d_in, const int* in_sizes, int n_in,
                              void* d_out, int out_size) {
    const float* X0 = (const float*)d_in[0];
    const float* head_r = (const float*)d_in[1];
    const float* tail_r = (const float*)d_in[2];
    const float* dual_A = (const float*)d_in[3];
    const int* erow = (const int*)d_in[4];
    const int* ecol = (const int*)d_in[5];
    const int* erel = (const int*)d_in[6];
    const int* mrow = (const int*)d_in[7];
    const int* mcol = (const int*)d_in[8];
    const float* mval = (const float*)d_in[9];
    const float* w_self1 = (const float*)d_in[10];
    const float* w_self2 = (const float*)d_in[11];
    const float* b_self2 = (const float*)d_in[12];
    const float* w_self3 = (const float*)d_in[13];
    const float* b_self3 = (const float*)d_in[14];
    const float* w_sp1 = (const float*)d_in[15];
    const float* b_sp1 = (const float*)d_in[16];
    const float* w_dual1 = (const float*)d_in[17];
    const float* w_dual2 = (const float*)d_in[18];
    const float* b_dual2 = (const float*)d_in[19];
    const float* w_dual3 = (const float*)d_in[20];
    const float* b_dual3 = (const float*)d_in[21];
    const float* w_sp2 = (const float*)d_in[22];
    const float* b_sp2 = (const float*)d_in[23];
    const float* w_gcn1 = (const float*)d_in[24];
    const float* w_gcn2 = (const float*)d_in[25];
    const float* k_hw1 = (const float*)d_in[26];
    const float* bg_hw1 = (const float*)d_in[27];
    const float* k_hw2 = (const float*)d_in[28];
    const float* bg_hw2 = (const float*)d_in[29];
    float* outp = (float*)d_out;

    float *pX2, *gb, *h1, *LR, *cs, *dX, *dH1, *dH2, *f1, *f2, *score, *valp;
    __nv_bfloat16 *Xbf, *Xbf2, *Xbf3, *HT, *XT, *KwT1, *KwT2, *coefbf, *valsT;
    int *cntE, *cntM, *curE, *curM, *erptr, *mrptr, *relp, *colpE, *colpM;
    cudaGetSymbolAddress((void**)&pX2, g_pX2);
    cudaGetSymbolAddress((void**)&gb, g_gb);
    cudaGetSymbolAddress((void**)&h1, g_h1);
    cudaGetSymbolAddress((void**)&Xbf, g_Xbf);
    cudaGetSymbolAddress((void**)&Xbf2, g_Xbf2);
    cudaGetSymbolAddress((void**)&Xbf3, g_Xbf3);
    cudaGetSymbolAddress((void**)&HT, g_HT);
    cudaGetSymbolAddress((void**)&XT, g_XT);
    cudaGetSymbolAddress((void**)&KwT1, g_KwT1);
    cudaGetSymbolAddress((void**)&KwT2, g_KwT2);
    cudaGetSymbolAddress((void**)&coefbf, g_coefbf);
    cudaGetSymbolAddress((void**)&valsT, g_valsT);
    cudaGetSymbolAddress((void**)&LR, g_LR);
    cudaGetSymbolAddress((void**)&cs, g_cs);
    cudaGetSymbolAddress((void**)&dX, g_dX);
    cudaGetSymbolAddress((void**)&dH1, g_dH1);
    cudaGetSymbolAddress((void**)&dH2, g_dH2);
    cudaGetSymbolAddress((void**)&f1, g_f1);
    cudaGetSymbolAddress((void**)&f2, g_f2);
    cudaGetSymbolAddress((void**)&score, g_score);
    cudaGetSymbolAddress((void**)&cntE, g_cntE);
    cudaGetSymbolAddress((void**)&cntM, g_cntM);
    cudaGetSymbolAddress((void**)&curE, g_curE);
    cudaGetSymbolAddress((void**)&curM, g_curM);
    cudaGetSymbolAddress((void**)&erptr, g_erptr);
    cudaGetSymbolAddress((void**)&mrptr, g_mrptr);
    cudaGetSymbolAddress((void**)&relp, g_relp);
    cudaGetSymbolAddress((void**)&colpE, g_colpE);
    cudaGetSymbolAddress((void**)&valp, g_valp);
    cudaGetSymbolAddress((void**)&colpM, g_colpM);

    const int T = 256;
    int gRD = (RN * DN + T - 1) / T;
    int gNE = (NEDGE + T - 1) / T;
    int gFW = (RN * 32 + T - 1) / T;
    int gRow = (EN * 32 + T - 1) / T;
    dim3 gHT(KP / 32, 32);   // fused head+tail transpose
    dim3 gTX9(KP / 32, 9);
    dim3 gPX(KP / 32, 9);
    dim3 gg(8, 2, GEMM_Z);
    dim3 gGate((EN + 127) / 128, DN / 128);
    dim3 gSm((RN + BM - 1) / BM, TWOD / BN);
    dim3 gTr(16, 16);

    // setup; launch 3 = fused big GEMM... keep GEMM in slot 4 with hist2 before it
    k_prepX_init<<<gPX, T>>>(X0, XT, Xbf, LR, cs, cntE, cntM, k_hw1, k_hw2, KwT1, KwT2);
    k_prepHT<<<gHT, T>>>(head_r, tail_r, HT, cs);
    k_hist2<<<gNE, T>>>(erow, mrow, cntE, cntM);
    k_gemm_tn<<<gg, T>>>(HT, XT, LR, 1000);
    k_norm<<<gRD, T>>>(LR, cs, dX);
    // CSR (payload-permuting scatter)
    k_scan2<<<1, 1024>>>(cntE, erptr, curE, cntM, mrptr, curM);
    k_scatter2<<<gNE, T>>>(erow, curE, erel, ecol, relp, colpE, mrow, curM, mval, mcol, valp,
                           colpM);
    // dense att 1
    k_f2<<<gFW, T>>>(w_self1, w_self2, w_self3, b_self2, b_self3, dX, f1, f2);
    k_coef<<<RN, 512>>>(f1, f2, dual_A, coefbf, b_sp1, score);
    k_transpT<<<gTr, T>>>(dX, valsT);
    k_gemm_small<<<gSm, T>>>(coefbf, valsT, dH1, w_sp1, score);
    // sparse att 1
    k_satt<<<gRow, T>>>(Xbf, X0, score, erptr, relp, colpE, 0.1f, (float*)0, Xbf2);
    // compute_r(pX1)
    k_transpTbf<<<gTX9, T>>>(Xbf2, XT, LR);
    k_gemm_tn<<<gg, T>>>(HT, XT, LR, 1000);
    k_norm<<<gRD, T>>>(LR, cs, dX);
    // dense att 2
    k_f2<<<gFW, T>>>(w_dual1, w_dual2, w_dual3, b_dual2, b_dual3, dX, f1, f2);
    k_coef<<<RN, 512>>>(f1, f2, dual_A, coefbf, b_sp2, score);
    k_transpT<<<gTr, T>>>(dH1, valsT);
    k_gemm_small<<<gSm, T>>>(coefbf, valsT, dH2, w_sp2, score);
    // sparse att 2
    k_satt<<<gRow, T>>>(Xbf2, X0, score, erptr, relp, colpE, 0.3f, pX2, Xbf3);
    // GCN + highway
    k_gcn<<<gRow, T>>>(Xbf3, w_gcn1, mrptr, valp, colpM, gb);
    k_gate128<<<gGate, T>>>(Xbf3, KwT1, bg_hw1, gb, pX2, h1, Xbf);
    k_gcn<<<gRow, T>>>(Xbf, w_gcn2, mrptr, valp, colpM, gb);
    k_gate128<<<gGate, T>>>(Xbf, KwT2, bg_hw2, gb, h1, outp, (__nv_bfloat16*)0);
}

// round 16
// speedup vs baseline: 1.6026x; 1.1197x over previous
#include <cuda_runtime.h>
#include <cuda_bf16.h>
#include <math.h>

#define EN 50000
#define RN 500
#define DN 256
#define NEDGE 500000
#define TWOD 512
#define HIDN 128
#define SLOPE 0.01f
#define KP 50048
#define TOTKB (KP / 32)
#define GEMM_Z 37
#define GEMM_KBPC 43
#define GSTR 40

// ---------------- static scratch ----------------
__device__ float g_pX2[EN * DN];
__device__ float g_gb[EN * DN];
__device__ float g_h1[EN * DN];
__device__ __nv_bfloat16 g_Xbf[EN * DN];
__device__ __nv_bfloat16 g_Xbf2[EN * DN];
__device__ __nv_bfloat16 g_Xbf3[EN * DN];
__device__ __nv_bfloat16 g_HT[1000 * KP];
__device__ __nv_bfloat16 g_XT[DN * KP];
__device__ __nv_bfloat16 g_KwT1[DN * DN];
__device__ __nv_bfloat16 g_KwT2[DN * DN];
__device__ __nv_bfloat16 g_coefbf[512 * 512];
__device__ __nv_bfloat16 g_valsT[512 * 512];
__device__ float g_LR[1000 * DN];
__device__ float g_cs[1000];
__device__ float g_dX[RN * TWOD];
__device__ float g_dH1[RN * TWOD];
__device__ float g_dH2[RN * TWOD];
__device__ float g_f1[RN];
__device__ float g_f2[RN];
__device__ float g_score[RN];
__device__ int g_cntE[EN];
__device__ int g_cntM[EN];
__device__ int g_curE[EN];
__device__ int g_curM[EN];
__device__ int g_erptr[EN + 1];
__device__ int g_mrptr[EN + 1];
__device__ int g_relp[NEDGE];
__device__ int g_colpE[NEDGE];
__device__ float g_valp[NEDGE];
__device__ int g_colpM[NEDGE];

// ---------------- fused X-transpose + global init + Kw prep ----------------
__global__ void k_prepX_init(const float* __restrict__ In, __nv_bfloat16* __restrict__ OutT,
                             __nv_bfloat16* __restrict__ Rowbf, float* __restrict__ LR,
                             float* __restrict__ cs, int* cE, int* cM,
                             const float* __restrict__ K1, const float* __restrict__ K2,
                             __nv_bfloat16* __restrict__ T1, __nv_bfloat16* __restrict__ T2) {
    if (blockIdx.y == 8) {
        int i = blockIdx.x * blockDim.x + threadIdx.x;
        if (i < 1000 * DN) LR[i] = 0.f;
        if (i < 1000) cs[i] = 0.f;
        if (i < EN) { cE[i] = 0; cM[i] = 0; }
        if (i < DN * DN) {
            int n = i >> 8, k = i & 255;
            T1[i] = __float2bfloat16(K1[k * DN + n]);
            T2[i] = __float2bfloat16(K2[k * DN + n]);
        }
        return;
    }
    __shared__ float tile[32][33];
    int e0 = blockIdx.x * 32, r0 = blockIdx.y * 32;
    int tx = threadIdx.x & 31, ty = threadIdx.x >> 5;
#pragma unroll
    for (int j = 0; j < 4; j++) {
        int e = e0 + ty + j * 8, r = r0 + tx;
        float v = (e < EN) ? In[(size_t)e * DN + r] : 0.f;
        tile[ty + j * 8][tx] = v;
        if (e < EN) Rowbf[(size_t)e * DN + r] = __float2bfloat16(v);
    }
    __syncthreads();
#pragma unroll
    for (int j = 0; j < 4; j++) {
        int r = r0 + ty + j * 8, e = e0 + tx;
        OutT[(size_t)r * KP + e] = __float2bfloat16(tile[tx][ty + j * 8]);
    }
}

// fused head+tail transpose
__global__ void k_prepHT(const float* __restrict__ Head, const float* __restrict__ Tail,
                         __nv_bfloat16* __restrict__ OutT, float* __restrict__ colsum) {
    __shared__ float tile[32][33];
    int isTail = blockIdx.y >= 16;
    const float* In = isTail ? Tail : Head;
    int r0 = (blockIdx.y - (isTail ? 16 : 0)) * 32;
    size_t obase = isTail ? (size_t)500 * KP : 0;
    int csoff = isTail ? 500 : 0;
    int e0 = blockIdx.x * 32;
    int tx = threadIdx.x & 31, ty = threadIdx.x >> 5;
#pragma unroll
    for (int j = 0; j < 4; j++) {
        int e = e0 + ty + j * 8, r = r0 + tx;
        tile[ty + j * 8][tx] = (e < EN && r < RN) ? In[(size_t)e * RN + r] : 0.f;
    }
    __syncthreads();
#pragma unroll
    for (int j = 0; j < 4; j++) {
        int r = r0 + ty + j * 8, e = e0 + tx;
        if (r < RN) OutT[obase + (size_t)r * KP + e] = __float2bfloat16(tile[tx][ty + j * 8]);
    }
    if (ty == 0 && r0 + tx < RN) {
        float s = 0.f;
#pragma unroll
        for (int e = 0; e < 32; e++) s += tile[e][tx];
        atomicAdd(&colsum[csoff + r0 + tx], s);
    }
}

// transpose bf16 [EN][DN] -> [DN][KP]; extra y-slice zeros LR
__global__ void k_transpTbf(const __nv_bfloat16* __restrict__ In,
                            __nv_bfloat16* __restrict__ OutT, float* __restrict__ LR) {
    if (blockIdx.y == 8) {
        int i = blockIdx.x * blockDim.x + threadIdx.x;
        if (i < 1000 * DN) LR[i] = 0.f;
        return;
    }
    __shared__ __nv_bfloat16 tile[32][33];
    int e0 = blockIdx.x * 32, r0 = blockIdx.y * 32;
    int tx = threadIdx.x & 31, ty = threadIdx.x >> 5;
#pragma unroll
    for (int j = 0; j < 4; j++) {
        int e = e0 + ty + j * 8, r = r0 + tx;
        tile[ty + j * 8][tx] = (e < EN) ? In[(size_t)e * DN + r] : __float2bfloat16(0.f);
    }
    __syncthreads();
#pragma unroll
    for (int j = 0; j < 4; j++) {
        int r = r0 + ty + j * 8, e = e0 + tx;
        OutT[(size_t)r * KP + e] = tile[tx][ty + j * 8];
    }
}

// vals [RN][512] fp32 -> valsT [512][512] bf16
__global__ void k_transpT(const float* __restrict__ in, __nv_bfloat16* __restrict__ out) {
    __shared__ float tile[32][33];
    int j0 = blockIdx.x * 32, d0 = blockIdx.y * 32;
    int tx = threadIdx.x & 31, ty = threadIdx.x >> 5;
#pragma unroll
    for (int jj = 0; jj < 4; jj++) {
        int j = j0 + ty + jj * 8;
        tile[ty + jj * 8][tx] = (j < RN) ? in[(size_t)j * TWOD + d0 + tx] : 0.f;
    }
    __syncthreads();
#pragma unroll
    for (int jj = 0; jj < 4; jj++) {
        int d = d0 + ty + jj * 8;
        out[(size_t)d * 512 + j0 + tx] = __float2bfloat16(tile[tx][ty + jj * 8]);
    }
}

// ---------------- CSR build ----------------
__global__ void k_hist2(const int* __restrict__ er, const int* __restrict__ mr, int* cE,
                        int* cM) {
    int i = blockIdx.x * blockDim.x + threadIdx.x;
    if (i < NEDGE) {
        atomicAdd(&cE[er[i]], 1);
        atomicAdd(&cM[mr[i]], 1);
    }
}
__global__ void k_scan2(const int* __restrict__ cA, int* __restrict__ pA, int* __restrict__ uA,
                        const int* __restrict__ cB, int* __restrict__ pB, int* __restrict__ uB) {
    __shared__ int wsum[32];
    __shared__ int s_run;
    int tid = threadIdx.x, lane = tid & 31, w = tid >> 5;
    for (int g = 0; g < 2; g++) {
        const int* cnt = g ? cB : cA;
        int* ptr = g ? pB : pA;
        int* cur = g ? uB : uA;
        if (tid == 0) s_run = 0;
        __syncthreads();
        for (int base = 0; base < EN; base += 1024) {
            int i = base + tid;
            int v = (i < EN) ? cnt[i] : 0;
            int x = v;
#pragma unroll
            for (int o = 1; o < 32; o <<= 1) {
                int y = __shfl_up_sync(0xffffffffu, x, o);
                if (lane >= o) x += y;
            }
            if (lane == 31) wsum[w] = x;
            __syncthreads();
            if (w == 0) {
                int s = wsum[lane];
#pragma unroll
                for (int o = 1; o < 32; o <<= 1) {
                    int y = __shfl_up_sync(0xffffffffu, s, o);
                    if (lane >= o) s += y;
                }
                wsum[lane] = s;
            }
            __syncthreads();
            int excl = s_run + x - v + (w ? wsum[w - 1] : 0);
            if (i < EN) { ptr[i] = excl; cur[i] = excl; }
            __syncthreads();
            if (tid == 1023) s_run += wsum[31];
            __syncthreads();
        }
        if (tid == 0) ptr[EN] = s_run;
        __syncthreads();
    }
}
__global__ void k_scatter2(const int* __restrict__ er, int* uE, const int* __restrict__ rel,
                           const int* __restrict__ ecol, int* __restrict__ relp,
                           int* __restrict__ colpE, const int* __restrict__ mr, int* uM,
                           const float* __restrict__ mval, const int* __restrict__ mcol,
                           float* __restrict__ valp, int* __restrict__ colpM) {
    int i = blockIdx.x * blockDim.x + threadIdx.x;
    if (i < NEDGE) {
        int pe_ = atomicAdd(&uE[er[i]], 1);
        relp[pe_] = rel[i];
        colpE[pe_] = ecol[i];
        int pm_ = atomicAdd(&uM[mr[i]], 1);
        valp[pm_] = mval[i];
        colpM[pm_] = mcol[i];
    }
}

// ---------------- mma helpers ----------------
__device__ __forceinline__ void mma16816(float* c, unsigned a0, unsigned a1, unsigned a2,
                                         unsigned a3, unsigned b0, unsigned b1) {
    asm volatile(
        "mma.sync.aligned.m16n8k16.row.col.f32.bf16.bf16.f32 "
        "{%0,%1,%2,%3},{%4,%5,%6,%7},{%8,%9},{%0,%1,%2,%3};\n"
        : "+f"(c[0]), "+f"(c[1]), "+f"(c[2]), "+f"(c[3])
        : "r"(a0), "r"(a1), "r"(a2), "r"(a3), "r"(b0), "r"(b1));
}
__device__ __forceinline__ void cpa16(unsigned s, const void* g) {
    asm volatile("cp.async.cg.shared.global [%0], [%1], 16;\n" ::"r"(s), "l"(g));
}
__device__ __forceinline__ void ldsm4(unsigned* r, unsigned addr) {
    asm volatile("ldmatrix.sync.aligned.m8n8.x4.shared.b16 {%0,%1,%2,%3}, [%4];\n"
                 : "=r"(r[0]), "=r"(r[1]), "=r"(r[2]), "=r"(r[3])
                 : "r"(addr));
}

// ---------------- fused big TN GEMM (BK=32, 2-stage, static smem, ldmatrix) -----------
__global__ __launch_bounds__(256) void k_gemm_tn(
    const __nv_bfloat16* __restrict__ A, const __nv_bfloat16* __restrict__ B,
    float* __restrict__ C, int M) {
    __shared__ __nv_bfloat16 As[2][128 * GSTR];
    __shared__ __nv_bfloat16 Bs[2][128 * GSTR];
    int t = threadIdx.x;
    int mbase = blockIdx.x * 128, nbase = blockIdx.y * 128;
    int kb0 = blockIdx.z * GEMM_KBPC;
    int kb1 = min(TOTKB, kb0 + GEMM_KBPC);
    if (kb0 >= kb1) return;
    int niter = kb1 - kb0;
    unsigned sA = (unsigned)__cvta_generic_to_shared(&As[0][0]);
    unsigned sB = (unsigned)__cvta_generic_to_shared(&Bs[0][0]);
    int row_ = t >> 2, ch = t & 3;
    const __nv_bfloat16* gA0 = A + (size_t)min(mbase + row_, M - 1) * KP + ch * 8;
    const __nv_bfloat16* gA1 = A + (size_t)min(mbase + 64 + row_, M - 1) * KP + ch * 8;
    const __nv_bfloat16* gB0 = B + (size_t)(nbase + row_) * KP + ch * 8;
    const __nv_bfloat16* gB1 = B + (size_t)(nbase + 64 + row_) * KP + ch * 8;
    unsigned oA0 = sA + (row_ * GSTR + ch * 8) * 2, oA1 = oA0 + 64 * GSTR * 2;
    unsigned oB0 = sB + (row_ * GSTR + ch * 8) * 2, oB1 = oB0 + 64 * GSTR * 2;
    const unsigned BUFB = 128 * GSTR * 2;
    {
        long k0 = (long)kb0 * 32;
        cpa16(oA0, gA0 + k0); cpa16(oA1, gA1 + k0);
        cpa16(oB0, gB0 + k0); cpa16(oB1, gB1 + k0);
        asm volatile("cp.async.commit_group;\n");
    }
    float c[2][8][4];
#pragma unroll
    for (int mt = 0; mt < 2; mt++)
#pragma unroll
        for (int f = 0; f < 8; f++)
#pragma unroll
            for (int i = 0; i < 4; i++) c[mt][f][i] = 0.f;
    int w = t >> 5, lane = t & 31;
    int wm = (w & 3) * 32, wn = (w >> 2) * 64;
    unsigned aoff = sA + ((wm + (lane & 15)) * GSTR + (lane >> 4) * 8) * 2;
    unsigned boff = sB + ((wn + (lane & 7) + ((lane >> 4) << 3)) * GSTR + ((lane >> 3) & 1) * 8) * 2;
    for (int i = 0; i < niter; i++) {
        int cur = i & 1, nxt = cur ^ 1;
        if (i + 1 < niter) {
            long k = (long)(kb0 + i + 1) * 32;
            cpa16(oA0 + nxt * BUFB, gA0 + k); cpa16(oA1 + nxt * BUFB, gA1 + k);
            cpa16(oB0 + nxt * BUFB, gB0 + k); cpa16(oB1 + nxt * BUFB, gB1 + k);
        }
        asm volatile("cp.async.commit_group;\n");
        asm volatile("cp.async.wait_group 1;\n");
        __syncthreads();
        unsigned aC = aoff + cur * BUFB, bC = boff + cur * BUFB;
#pragma unroll
        for (int kk = 0; kk < 32; kk += 16) {
            unsigned A0[4], A1[4];
            ldsm4(A0, aC + kk * 2);
            ldsm4(A1, aC + (16 * GSTR + kk) * 2);
#pragma unroll
            for (int p = 0; p < 4; p++) {
                unsigned B4[4];
                ldsm4(B4, bC + (p * 16 * GSTR + kk) * 2);
                mma16816(c[0][2 * p], A0[0], A0[1], A0[2], A0[3], B4[0], B4[1]);
                mma16816(c[1][2 * p], A1[0], A1[1], A1[2], A1[3], B4[0], B4[1]);
                mma16816(c[0][2 * p + 1], A0[0], A0[1], A0[2], A0[3], B4[2], B4[3]);
                mma16816(c[1][2 * p + 1], A1[0], A1[1], A1[2], A1[3], B4[2], B4[3]);
            }
        }
        __syncthreads();
    }
    int gi = lane >> 2, qp = lane & 3;
#pragma unroll
    for (int mt = 0; mt < 2; mt++)
#pragma unroll
        for (int f = 0; f < 8; f++) {
            int gm0 = mbase + wm + mt * 16 + gi, gm1 = gm0 + 8;
            int gn = nbase + wn + f * 8 + qp * 2;
            if (gm0 < M) {
                atomicAdd(&C[gm0 * DN + gn], c[mt][f][0]);
                atomicAdd(&C[gm0 * DN + gn + 1], c[mt][f][1]);
            }
            if (gm1 < M) {
                atomicAdd(&C[gm1 * DN + gn], c[mt][f][2]);
                atomicAdd(&C[gm1 * DN + gn + 1], c[mt][f][3]);
            }
        }
}

// ---------------- gate GEMM (BK=32, K=256, static smem, highway fused, ldmatrix) ------
__global__ __launch_bounds__(256) void k_gate128(
    const __nv_bfloat16* __restrict__ Abf, const __nv_bfloat16* __restrict__ KwT,
    const float* __restrict__ bg, const float* __restrict__ G, const float* __restrict__ L1,
    float* __restrict__ H, __nv_bfloat16* __restrict__ Hbf) {
    __shared__ __nv_bfloat16 As[2][128 * GSTR];
    __shared__ __nv_bfloat16 Bs[2][128 * GSTR];
    int t = threadIdx.x;
    int mbase = blockIdx.x * 128, nbase = blockIdx.y * 128;
    unsigned sA = (unsigned)__cvta_generic_to_shared(&As[0][0]);
    unsigned sB = (unsigned)__cvta_generic_to_shared(&Bs[0][0]);
    int row_ = t >> 2, ch = t & 3;
    const __nv_bfloat16* gA0 = Abf + (size_t)min(mbase + row_, EN - 1) * DN + ch * 8;
    const __nv_bfloat16* gA1 = Abf + (size_t)min(mbase + 64 + row_, EN - 1) * DN + ch * 8;
    const __nv_bfloat16* gB0 = KwT + (size_t)(nbase + row_) * DN + ch * 8;
    const __nv_bfloat16* gB1 = KwT + (size_t)(nbase + 64 + row_) * DN + ch * 8;
    unsigned oA0 = sA + (row_ * GSTR + ch * 8) * 2, oA1 = oA0 + 64 * GSTR * 2;
    unsigned oB0 = sB + (row_ * GSTR + ch * 8) * 2, oB1 = oB0 + 64 * GSTR * 2;
    const unsigned BUFB = 128 * GSTR * 2;
    cpa16(oA0, gA0); cpa16(oA1, gA1);
    cpa16(oB0, gB0); cpa16(oB1, gB1);
    asm volatile("cp.async.commit_group;\n");
    float c[2][8][4];
#pragma unroll
    for (int mt = 0; mt < 2; mt++)
#pragma unroll
        for (int f = 0; f < 8; f++)
#pragma unroll
            for (int i = 0; i < 4; i++) c[mt][f][i] = 0.f;
    int w = t >> 5, lane = t & 31;
    int wm = (w & 3) * 32, wn = (w >> 2) * 64;
    unsigned aoff = sA + ((wm + (lane & 15)) * GSTR + (lane >> 4) * 8) * 2;
    unsigned boff = sB + ((wn + (lane & 7) + ((lane >> 4) << 3)) * GSTR + ((lane >> 3) & 1) * 8) * 2;
    const int NIT = DN / 32;
#pragma unroll
    for (int i = 0; i < NIT; i++) {
        int cur = i & 1, nxt = cur ^ 1;
        if (i + 1 < NIT) {
            int k = (i + 1) * 32;
            cpa16(oA0 + nxt * BUFB, gA0 + k); cpa16(oA1 + nxt * BUFB, gA1 + k);
            cpa16(oB0 + nxt * BUFB, gB0 + k); cpa16(oB1 + nxt * BUFB, gB1 + k);
        }
        asm volatile("cp.async.commit_group;\n");
        asm volatile("cp.async.wait_group 1;\n");
        __syncthreads();
        unsigned aC = aoff + cur * BUFB, bC = boff + cur * BUFB;
#pragma unroll
        for (int kk = 0; kk < 32; kk += 16) {
            unsigned A0[4], A1[4];
            ldsm4(A0, aC + kk * 2);
            ldsm4(A1, aC + (16 * GSTR + kk) * 2);
#pragma unroll
            for (int p = 0; p < 4; p++) {
                unsigned B4[4];
                ldsm4(B4, bC + (p * 16 * GSTR + kk) * 2);
                mma16816(c[0][2 * p], A0[0], A0[1], A0[2], A0[3], B4[0], B4[1]);
                mma16816(c[1][2 * p], A1[0], A1[1], A1[2], A1[3], B4[0], B4[1]);
                mma16816(c[0][2 * p + 1], A0[0], A0[1], A0[2], A0[3], B4[2], B4[3]);
                mma16816(c[1][2 * p + 1], A1[0], A1[1], A1[2], A1[3], B4[2], B4[3]);
            }
        }
        __syncthreads();
    }
    int gi = lane >> 2, qp = lane & 3;
#pragma unroll
    for (int mt = 0; mt < 2; mt++)
#pragma unroll
        for (int f = 0; f < 8; f++) {
            int gn = nbase + wn + f * 8 + qp * 2;
#pragma unroll
            for (int half = 0; half < 2; half++) {
                int gm = mbase + wm + mt * 16 + gi + half * 8;
                if (gm < EN) {
#pragma unroll
                    for (int j = 0; j < 2; j++) {
                        float z = c[mt][f][half * 2 + j] + bg[gn + j];
                        float tg = 1.f / (1.f + __expf(-z));
                        size_t off = (size_t)gm * DN + gn + j;
                        float hv = tg * G[off] + (1.f - tg) * L1[off];
                        H[off] = hv;
                        if (Hbf) Hbf[off] = __float2bfloat16(hv);
                    }
                }
            }
        }
}

// ------- small dense-att GEMM: dH = relu(coef @ valsT^T), K=512, + fused score -------
#define BM 64
#define BN 64
#define BKK 32
#define ASTR 40
__global__ __launch_bounds__(256) void k_gemm_small(const __nv_bfloat16* __restrict__ A,
                                                    const __nv_bfloat16* __restrict__ B,
                                                    float* __restrict__ C,
                                                    const float* __restrict__ wsp,
                                                    float* __restrict__ score) {
    __shared__ __nv_bfloat16 Asm[BM * ASTR];
    __shared__ __nv_bfloat16 Bsm[BN * ASTR];
    int t = threadIdx.x;
    int mbase = blockIdx.x * BM, nbase = blockIdx.y * BN;
    int w = t >> 5, lane = t & 31;
    int wm = (w & 3) * 16, wn = (w >> 2) * 32;
    int row = lane >> 2, qp = lane & 3;
    float c[4][4];
#pragma unroll
    for (int f = 0; f < 4; f++)
#pragma unroll
        for (int i = 0; i < 4; i++) c[f][i] = 0.f;
    for (int kb = 0; kb < 512; kb += BKK) {
#pragma unroll
        for (int i = 0; i < 8; i++) {
            int idx = t + i * 256;
            int m = idx >> 5, k = idx & 31;
            int gm = min(mbase + m, RN - 1);
            Asm[m * ASTR + k] = A[(size_t)gm * 512 + kb + k];
        }
#pragma unroll
        for (int i = 0; i < 8; i++) {
            int idx = t + i * 256;
            int n = idx >> 5, k = idx & 31;
            Bsm[n * ASTR + k] = B[(size_t)(nbase + n) * 512 + kb + k];
        }
        __syncthreads();
#pragma unroll
        for (int kk = 0; kk < BKK; kk += 16) {
            unsigned a0 = *(const unsigned*)&Asm[(wm + row) * ASTR + kk + qp * 2];
            unsigned a1 = *(const unsigned*)&Asm[(wm + row + 8) * ASTR + kk + qp * 2];
            unsigned a2 = *(const unsigned*)&Asm[(wm + row) * ASTR + kk + 8 + qp * 2];
            unsigned a3 = *(const unsigned*)&Asm[(wm + row + 8) * ASTR + kk + 8 + qp * 2];
#pragma unroll
            for (int f = 0; f < 4; f++) {
                unsigned b0 = *(const unsigned*)&Bsm[(wn + f * 8 + row) * ASTR + kk + qp * 2];
                unsigned b1 = *(const unsigned*)&Bsm[(wn + f * 8 + row) * ASTR + kk + 8 + qp * 2];
                mma16816(c[f], a0, a1, a2, a3, b0, b1);
            }
        }
        __syncthreads();
    }
    float p0 = 0.f, p1 = 0.f;
    int gm0 = mbase + wm + row, gm1 = gm0 + 8;
#pragma unroll
    for (int f = 0; f < 4; f++) {
        int gn = nbase + wn + f * 8 + qp * 2;
        float w0 = wsp[gn], w1v = wsp[gn + 1];
        float r00 = fmaxf(c[f][0], 0.f), r01 = fmaxf(c[f][1], 0.f);
        float r10 = fmaxf(c[f][2], 0.f), r11 = fmaxf(c[f][3], 0.f);
        if (gm0 < RN) {
            C[(size_t)gm0 * TWOD + gn] = r00;
            C[(size_t)gm0 * TWOD + gn + 1] = r01;
        }
        if (gm1 < RN) {
            C[(size_t)gm1 * TWOD + gn] = r10;
            C[(size_t)gm1 * TWOD + gn + 1] = r11;
        }
        p0 += r00 * w0 + r01 * w1v;
        p1 += r10 * w0 + r11 * w1v;
    }
    p0 += __shfl_xor_sync(0xffffffffu, p0, 1);
    p0 += __shfl_xor_sync(0xffffffffu, p0, 2);
    p1 += __shfl_xor_sync(0xffffffffu, p1, 1);
    p1 += __shfl_xor_sync(0xffffffffu, p1, 2);
    if (qp == 0) {
        if (gm0 < RN) atomicAdd(&score[gm0], p0);
        if (gm1 < RN) atomicAdd(&score[gm1], p1);
    }
}

// ---------------- small compute kernels ----------------
__global__ void k_norm(const float* __restrict__ LR, const float* __restrict__ cs,
                       float* __restrict__ dX) {
    int i = blockIdx.x * blockDim.x + threadIdx.x;
    if (i < RN * DN) {
        int r = i >> 8, d = i & 255;
        dX[r * TWOD + d] = LR[i] / cs[r];
        dX[r * TWOD + DN + d] = LR[RN * DN + i] / cs[RN + r];
    }
}
__device__ __forceinline__ float warpSum(float v) {
#pragma unroll
    for (int o = 16; o; o >>= 1) v += __shfl_xor_sync(0xffffffffu, v, o);
    return v;
}
__device__ __forceinline__ float warpMax(float v) {
#pragma unroll
    for (int o = 16; o; o >>= 1) v = fmaxf(v, __shfl_xor_sync(0xffffffffu, v, o));
    return v;
}
__global__ __launch_bounds__(256) void k_f2(
    const float* __restrict__ w1, const float* __restrict__ w2, const float* __restrict__ w3,
    const float* __restrict__ b2, const float* __restrict__ b3,
    const float* __restrict__ feats, float* __restrict__ f1, float* __restrict__ f2) {
    __shared__ float v1s[TWOD], v2s[TWOD];
    int tid = threadIdx.x;
    for (int i = tid; i < TWOD; i += 256) {
        float s1 = 0.f, s2 = 0.f;
        for (int h = 0; h < HIDN; h++) {
            float w = w1[h * TWOD + i];
            s1 += w2[h] * w;
            s2 += w3[h] * w;
        }
        v1s[i] = s1;
        v2s[i] = s2;
    }
    __syncthreads();
    int gw = (blockIdx.x * 256 + tid) >> 5;
    int lane = tid & 31;
    if (gw >= RN) return;
    float s1 = 0.f, s2 = 0.f;
    for (int i = lane; i < TWOD; i += 32) {
        float x = feats[gw * TWOD + i];
        s1 += x * v1s[i];
        s2 += x * v2s[i];
    }
    s1 = warpSum(s1);
    s2 = warpSum(s2);
    if (lane == 0) { f1[gw] = s1 + b2[0]; f2[gw] = s2 + b3[0]; }
}
__global__ __launch_bounds__(512) void k_coef(const float* __restrict__ f1,
                                              const float* __restrict__ f2,
                                              const float* __restrict__ adj,
                                              __nv_bfloat16* __restrict__ coefbf,
                                              const float* __restrict__ bsp,
                                              float* __restrict__ score) {
    int r = blockIdx.x;
    int tid = threadIdx.x;
    __shared__ float red[512];
    if (tid == 0) score[r] = bsp[0];
    float f1r = f1[r];
    float l = -INFINITY;
    if (tid < RN) {
        float a = adj[r * RN + tid];
        float x = a * (f1r + f2[tid]);
        l = x > 0.f ? x : SLOPE * x;
        if (!(a > 0.f)) l -= 1e9f;
    }
    red[tid] = l;
    __syncthreads();
    for (int s = 256; s > 0; s >>= 1) {
        if (tid < s) red[tid] = fmaxf(red[tid], red[tid + s]);
        __syncthreads();
    }
    float mx = red[0];
    __syncthreads();
    float e = (tid < RN) ? __expf(l - mx) : 0.f;
    red[tid] = e;
    __syncthreads();
    for (int s = 256; s > 0; s >>= 1) {
        if (tid < s) red[tid] += red[tid + s];
        __syncthreads();
    }
    float inv = 1.f / red[0];
    coefbf[(size_t)r * 512 + tid] = __float2bfloat16(e * inv);
}
// sparse attention: warp/row, smem leaky-score LUT, permuted payloads, bf16 gather
__global__ __launch_bounds__(256) void k_satt(
    const __nv_bfloat16* __restrict__ Xsrc, const float* __restrict__ Xres,
    const float* __restrict__ score, const int* __restrict__ rptr,
    const int* __restrict__ relp, const int* __restrict__ colp,
    float alpha, float* __restrict__ out, __nv_bfloat16* __restrict__ outbf) {
    __shared__ float lsc[RN];
    int tid = threadIdx.x;
    for (int i = tid; i < RN; i += 256) {
        float sc = score[i];
        lsc[i] = sc > 0.f ? sc : SLOPE * sc;
    }
    __syncthreads();
    int e = (blockIdx.x * blockDim.x + tid) >> 5;
    int lane = tid & 31;
    if (e >= EN) return;
    int s = rptr[e], t = rptr[e + 1];
    float acc[8];
#pragma unroll
    for (int i = 0; i < 8; i++) acc[i] = 0.f;
    if (t > s) {
        float m = -1e30f;
        for (int j = s + lane; j < t; j += 32) m = fmaxf(m, lsc[relp[j]]);
        m = warpMax(m);
        float ssum = 0.f;
        for (int j = s + lane; j < t; j += 32) ssum += __expf(lsc[relp[j]] - m);
        ssum = warpSum(ssum);
        float inv = 1.f / ssum;
        int j = s;
        for (; j + 1 < t; j += 2) {
            float cf0 = __expf(lsc[relp[j]] - m) * inv;
            float cf1 = __expf(lsc[relp[j + 1]] - m) * inv;
            uint4 v0 = ((const uint4*)(Xsrc + (size_t)colp[j] * DN))[lane];
            uint4 v1 = ((const uint4*)(Xsrc + (size_t)colp[j + 1] * DN))[lane];
            float2 p;
            p = __bfloat1622float2(*(const __nv_bfloat162*)&v0.x);
            acc[0] += cf0 * p.x; acc[1] += cf0 * p.y;
            p = __bfloat1622float2(*(const __nv_bfloat162*)&v0.y);
            acc[2] += cf0 * p.x; acc[3] += cf0 * p.y;
            p = __bfloat1622float2(*(const __nv_bfloat162*)&v0.z);
            acc[4] += cf0 * p.x; acc[5] += cf0 * p.y;
            p = __bfloat1622float2(*(const __nv_bfloat162*)&v0.w);
            acc[6] += cf0 * p.x; acc[7] += cf0 * p.y;
            p = __bfloat1622float2(*(const __nv_bfloat162*)&v1.x);
            acc[0] += cf1 * p.x; acc[1] += cf1 * p.y;
            p = __bfloat1622float2(*(const __nv_bfloat162*)&v1.y);
            acc[2] += cf1 * p.x; acc[3] += cf1 * p.y;
            p = __bfloat1622float2(*(const __nv_bfloat162*)&v1.z);
            acc[4] += cf1 * p.x; acc[5] += cf1 * p.y;
            p = __bfloat1622float2(*(const __nv_bfloat162*)&v1.w);
            acc[6] += cf1 * p.x; acc[7] += cf1 * p.y;
        }
        if (j < t) {
            float cf = __expf(lsc[relp[j]] - m) * inv;
            uint4 v = ((const uint4*)(Xsrc + (size_t)colp[j] * DN))[lane];
            float2 p;
            p = __bfloat1622float2(*(const __nv_bfloat162*)&v.x);
            acc[0] += cf * p.x; acc[1] += cf * p.y;
            p = __bfloat1622float2(*(const __nv_bfloat162*)&v.y);
            acc[2] += cf * p.x; acc[3] += cf * p.y;
            p = __bfloat1622float2(*(const __nv_bfloat162*)&v.z);
            acc[4] += cf * p.x; acc[5] += cf * p.y;
            p = __bfloat1622float2(*(const __nv_bfloat162*)&v.w);
            acc[6] += cf * p.x; acc[7] += cf * p.y;
        }
    }
    size_t base = (size_t)e * DN;
    const float4* rr = (const float4*)(Xres + base);
    float4 r0 = rr[lane * 2], r1 = rr[lane * 2 + 1];
    float o[8];
    o[0] = r0.x + alpha * fmaxf(acc[0], 0.f);
    o[1] = r0.y + alpha * fmaxf(acc[1], 0.f);
    o[2] = r0.z + alpha * fmaxf(acc[2], 0.f);
    o[3] = r0.w + alpha * fmaxf(acc[3], 0.f);
    o[4] = r1.x + alpha * fmaxf(acc[4], 0.f);
    o[5] = r1.y + alpha * fmaxf(acc[5], 0.f);
    o[6] = r1.z + alpha * fmaxf(acc[6], 0.f);
    o[7] = r1.w + alpha * fmaxf(acc[7], 0.f);
    if (out) {
        ((float4*)(out + base))[lane * 2] = make_float4(o[0], o[1], o[2], o[3]);
        ((float4*)(out + base))[lane * 2 + 1] = make_float4(o[4], o[5], o[6], o[7]);
    }
    __nv_bfloat162 b0 = __floats2bfloat162_rn(o[0], o[1]);
    __nv_bfloat162 b1 = __floats2bfloat162_rn(o[2], o[3]);
    __nv_bfloat162 b2 = __floats2bfloat162_rn(o[4], o[5]);
    __nv_bfloat162 b3 = __floats2bfloat162_rn(o[6], o[7]);
    uint4 ob;
    ob.x = *(unsigned*)&b0; ob.y = *(unsigned*)&b1;
    ob.z = *(unsigned*)&b2; ob.w = *(unsigned*)&b3;
    ((uint4*)(outbf + base))[lane] = ob;
}
// GCN: warp/row, permuted payloads, bf16 gather (2-edge unrolled)
__global__ __launch_bounds__(256) void k_gcn(
    const __nv_bfloat16* __restrict__ X, const float* __restrict__ w,
    const int* __restrict__ rptr, const float* __restrict__ valp,
    const int* __restrict__ colp, float* __restrict__ out) {
    int e = (blockIdx.x * blockDim.x + threadIdx.x) >> 5;
    int lane = threadIdx.x & 31;
    if (e >= EN) return;
    int s = rptr[e], t = rptr[e + 1];
    float acc[8];
#pragma unroll
    for (int i = 0; i < 8; i++) acc[i] = 0.f;
    int j = s;
    for (; j + 1 < t; j += 2) {
        float v0s = valp[j], v1s = valp[j + 1];
        uint4 u0 = ((const uint4*)(X + (size_t)colp[j] * DN))[lane];
        uint4 u1 = ((const uint4*)(X + (size_t)colp[j + 1] * DN))[lane];
        float2 p;
        p = __bfloat1622float2(*(const __nv_bfloat162*)&u0.x);
        acc[0] += v0s * p.x; acc[1] += v0s * p.y;
        p = __bfloat1622float2(*(const __nv_bfloat162*)&u0.y);
        acc[2] += v0s * p.x; acc[3] += v0s * p.y;
        p = __bfloat1622float2(*(const __nv_bfloat162*)&u0.z);
        acc[4] += v0s * p.x; acc[5] += v0s * p.y;
        p = __bfloat1622float2(*(const __nv_bfloat162*)&u0.w);
        acc[6] += v0s * p.x; acc[7] += v0s * p.y;
        p = __bfloat1622float2(*(const __nv_bfloat162*)&u1.x);
        acc[0] += v1s * p.x; acc[1] += v1s * p.y;
        p = __bfloat1622float2(*(const __nv_bfloat162*)&u1.y);
        acc[2] += v1s * p.x; acc[3] += v1s * p.y;
        p = __bfloat1622float2(*(const __nv_bfloat162*)&u1.z);
        acc[4] += v1s * p.x; acc[5] += v1s * p.y;
        p = __bfloat1622float2(*(const __nv_bfloat162*)&u1.w);
        acc[6] += v1s * p.x; acc[7] += v1s * p.y;
    }
    if (j < t) {
        float v = valp[j];
        uint4 u = ((const uint4*)(X + (size_t)colp[j] * DN))[lane];
        float2 p;
        p = __bfloat1622float2(*(const __nv_bfloat162*)&u.x);
        acc[0] += v * p.x; acc[1] += v * p.y;
        p = __bfloat1622float2(*(const __nv_bfloat162*)&u.y);
        acc[2] += v * p.x; acc[3] += v * p.y;
        p = __bfloat1622float2(*(const __nv_bfloat162*)&u.z);
        acc[4] += v * p.x; acc[5] += v * p.y;
        p = __bfloat1622float2(*(const __nv_bfloat162*)&u.w);
        acc[6] += v * p.x; acc[7] += v * p.y;
    }
    size_t base = (size_t)e * DN;
    int d = lane * 8;
    float4 o0 = make_float4(fmaxf(acc[0] * w[d], 0.f), fmaxf(acc[1] * w[d + 1], 0.f),
                            fmaxf(acc[2] * w[d + 2], 0.f), fmaxf(acc[3] * w[d + 3], 0.f));
    float4 o1 = make_float4(fmaxf(acc[4] * w[d + 4], 0.f), fmaxf(acc[5] * w[d + 5], 0.f),
                            fmaxf(acc[6] * w[d + 6], 0.f), fmaxf(acc[7] * w[d + 7], 0.f));
    ((float4*)(out + base))[lane * 2] = o0;
    ((float4*)(out + base))[lane * 2 + 1] = o1;
}

// ---------------- host ----------------
extern "C" void kernel_launch(void* const* d_in, const int* in_sizes, int n_in,
                              void* d_out, int out_size) {
    const float* X0 = (const float*)d_in[0];
    const float* head_r = (const float*)d_in[1];
    const float* tail_r = (const float*)d_in[2];
    const float* dual_A = (const float*)d_in[3];
    const int* erow = (const int*)d_in[4];
    const int* ecol = (const int*)d_in[5];
    const int* erel = (const int*)d_in[6];
    const int* mrow = (const int*)d_in[7];
    const int* mcol = (const int*)d_in[8];
    const float* mval = (const float*)d_in[9];
    const float* w_self1 = (const float*)d_in[10];
    const float* w_self2 = (const float*)d_in[11];
    const float* b_self2 = (const float*)d_in[12];
    const float* w_self3 = (const float*)d_in[13];
    const float* b_self3 = (const float*)d_in[14];
    const float* w_sp1 = (const float*)d_in[15];
    const float* b_sp1 = (const float*)d_in[16];
    const float* w_dual1 = (const float*)d_in[17];
    const float* w_dual2 = (const float*)d_in[18];
    const float* b_dual2 = (const float*)d_in[19];
    const float* w_dual3 = (const float*)d_in[20];
    const float* b_dual3 = (const float*)d_in[21];
    const float* w_sp2 = (const float*)d_in[22];
    const float* b_sp2 = (const float*)d_in[23];
    const float* w_gcn1 = (const float*)d_in[24];
    const float* w_gcn2 = (const float*)d_in[25];
    const float* k_hw1 = (const float*)d_in[26];
    const float* bg_hw1 = (const float*)d_in[27];
    const float* k_hw2 = (const float*)d_in[28];
    const float* bg_hw2 = (const float*)d_in[29];
    float* outp = (float*)d_out;

    float *pX2, *gb, *h1, *LR, *cs, *dX, *dH1, *dH2, *f1, *f2, *score, *valp;
    __nv_bfloat16 *Xbf, *Xbf2, *Xbf3, *HT, *XT, *KwT1, *KwT2, *coefbf, *valsT;
    int *cntE, *cntM, *curE, *curM, *erptr, *mrptr, *relp, *colpE, *colpM;
    cudaGetSymbolAddress((void**)&pX2, g_pX2);
    cudaGetSymbolAddress((void**)&gb, g_gb);
    cudaGetSymbolAddress((void**)&h1, g_h1);
    cudaGetSymbolAddress((void**)&Xbf, g_Xbf);
    cudaGetSymbolAddress((void**)&Xbf2, g_Xbf2);
    cudaGetSymbolAddress((void**)&Xbf3, g_Xbf3);
    cudaGetSymbolAddress((void**)&HT, g_HT);
    cudaGetSymbolAddress((void**)&XT, g_XT);
    cudaGetSymbolAddress((void**)&KwT1, g_KwT1);
    cudaGetSymbolAddress((void**)&KwT2, g_KwT2);
    cudaGetSymbolAddress((void**)&coefbf, g_coefbf);
    cudaGetSymbolAddress((void**)&valsT, g_valsT);
    cudaGetSymbolAddress((void**)&LR, g_LR);
    cudaGetSymbolAddress((void**)&cs, g_cs);
    cudaGetSymbolAddress((void**)&dX, g_dX);
    cudaGetSymbolAddress((void**)&dH1, g_dH1);
    cudaGetSymbolAddress((void**)&dH2, g_dH2);
    cudaGetSymbolAddress((void**)&f1, g_f1);
    cudaGetSymbolAddress((void**)&f2, g_f2);
    cudaGetSymbolAddress((void**)&score, g_score);
    cudaGetSymbolAddress((void**)&cntE, g_cntE);
    cudaGetSymbolAddress((void**)&cntM, g_cntM);
    cudaGetSymbolAddress((void**)&curE, g_curE);
    cudaGetSymbolAddress((void**)&curM, g_curM);
    cudaGetSymbolAddress((void**)&erptr, g_erptr);
    cudaGetSymbolAddress((void**)&mrptr, g_mrptr);
    cudaGetSymbolAddress((void**)&relp, g_relp);
    cudaGetSymbolAddress((void**)&colpE, g_colpE);
    cudaGetSymbolAddress((void**)&valp, g_valp);
    cudaGetSymbolAddress((void**)&colpM, g_colpM);

    // one-time side stream + fork/join events (same GPU work every call)
    static cudaStream_t s2 = 0;
    static cudaEvent_t evA = 0, evB = 0, evC = 0, evD = 0;
    if (!s2) {
        cudaStreamCreateWithFlags(&s2, cudaStreamNonBlocking);
        cudaEventCreateWithFlags(&evA, cudaEventDisableTiming);
        cudaEventCreateWithFlags(&evB, cudaEventDisableTiming);
        cudaEventCreateWithFlags(&evC, cudaEventDisableTiming);
        cudaEventCreateWithFlags(&evD, cudaEventDisableTiming);
    }

    const int T = 256;
    int gRD = (RN * DN + T - 1) / T;
    int gNE = (NEDGE + T - 1) / T;
    int gFW = (RN * 32 + T - 1) / T;
    int gRow = (EN * 32 + T - 1) / T;
    dim3 gHT(KP / 32, 32);
    dim3 gTX9(KP / 32, 9);
    dim3 gPX(KP / 32, 9);
    dim3 gg(8, 2, GEMM_Z);
    dim3 gGate((EN + 127) / 128, DN / 128);
    dim3 gSm((RN + BM - 1) / BM, TWOD / BN);
    dim3 gTr(16, 16);

    // setup (zeroes CSR histograms too)
    k_prepX_init<<<gPX, T>>>(X0, XT, Xbf, LR, cs, cntE, cntM, k_hw1, k_hw2, KwT1, KwT2);
    // ---- fork: CSR branch on s2, overlapped with GEMM + dense-att chain ----
    cudaEventRecord(evA, 0);
    cudaStreamWaitEvent(s2, evA, 0);
    k_hist2<<<gNE, T, 0, s2>>>(erow, mrow, cntE, cntM);
    k_scan2<<<1, 1024, 0, s2>>>(cntE, erptr, curE, cntM, mrptr, curM);
    k_scatter2<<<gNE, T, 0, s2>>>(erow, curE, erel, ecol, relp, colpE, mrow, curM, mval, mcol,
                                  valp, colpM);
    cudaEventRecord(evB, s2);
    // ---- main chain ----
    k_prepHT<<<gHT, T>>>(head_r, tail_r, HT, cs);
    k_gemm_tn<<<gg, T>>>(HT, XT, LR, 1000);
    k_norm<<<gRD, T>>>(LR, cs, dX);
    // dense att 1
    k_f2<<<gFW, T>>>(w_self1, w_self2, w_self3, b_self2, b_self3, dX, f1, f2);
    k_coef<<<RN, 512>>>(f1, f2, dual_A, coefbf, b_sp1, score);
    k_transpT<<<gTr, T>>>(dX, valsT);
    k_gemm_small<<<gSm, T>>>(coefbf, valsT, dH1, w_sp1, score);
    // fork: layer-2 vals transpose on s2 (after gemm_small1 finished reading valsT)
    cudaEventRecord(evC, 0);
    cudaStreamWaitEvent(s2, evC, 0);
    k_transpT<<<gTr, T, 0, s2>>>(dH1, valsT);
    cudaEventRecord(evD, s2);
    // join CSR before sparse att 1
    cudaStreamWaitEvent(0, evB, 0);
    k_satt<<<gRow, T>>>(Xbf, X0, score, erptr, relp, colpE, 0.1f, (float*)0, Xbf2);
    // compute_r(pX1)
    k_transpTbf<<<gTX9, T>>>(Xbf2, XT, LR);
    k_gemm_tn<<<gg, T>>>(HT, XT, LR, 1000);
    k_norm<<<gRD, T>>>(LR, cs, dX);
    // dense att 2
    k_f2<<<gFW, T>>>(w_dual1, w_dual2, w_dual3, b_dual2, b_dual3, dX, f1, f2);
    k_coef<<<RN, 512>>>(f1, f2, dual_A, coefbf, b_sp2, score);
    cudaStreamWaitEvent(0, evD, 0);  // join valsT(dH1)
    k_gemm_small<<<gSm, T>>>(coefbf, valsT, dH2, w_sp2, score);
    // sparse att 2
    k_satt<<<gRow, T>>>(Xbf2, X0, score, erptr, relp, colpE, 0.3f, pX2, Xbf3);
    // GCN + highway
    k_gcn<<<gRow, T>>>(Xbf3, w_gcn1, mrptr, valp, colpM, gb);
    k_gate128<<<gGate, T>>>(Xbf3, KwT1, bg_hw1, gb, pX2, h1, Xbf);
    k_gcn<<<gRow, T>>>(Xbf, w_gcn2, mrptr, valp, colpM, gb);
    k_gate128<<<gGate, T>>>(Xbf, KwT2, bg_hw2, gb, h1, outp, (__nv_bfloat16*)0);
}